// round 1
// baseline (speedup 1.0000x reference)
#include <cuda_runtime.h>
#include <math.h>

// Problem constants (shapes are fixed by the dataset).
#define BSZ  8192
#define INPD 3072
#define HIDD 1024
#define OUTD 768
#define LN_EPS 1e-5f

// ---------------------------------------------------------------------------
// Scratch: __device__ globals (no allocations allowed in kernel_launch).
// ---------------------------------------------------------------------------
__device__ float g_mean[BSZ];
__device__ float g_rstd[BSZ];
__device__ float g_H[(size_t)BSZ * HIDD];     // backbone activations
__device__ float g_T[(size_t)BSZ * HIDD];     // relu(H@Wa+ba)
__device__ float g_P[(size_t)BSZ * OUTD];     // pre-LN2 output
__device__ float g_PN[(size_t)BSZ * OUTD];    // normalized pred
__device__ float g_YN[(size_t)BSZ * OUTD];    // normalized y
__device__ float g_S[(size_t)BSZ * BSZ];      // cosine-sim matrix (256 MB)
__device__ double g_loss;
__device__ int    g_correct;

// ---------------------------------------------------------------------------
__global__ void zero_accum_kernel() {
    g_loss = 0.0;
    g_correct = 0;
}

// Per-row mean / rstd of inp (for fusing LN1 into GEMM1's A-load).
__global__ void row_meanvar_kernel(const float* __restrict__ x) {
    int row = blockIdx.x;
    const float* xr = x + (size_t)row * INPD;
    float s = 0.f, ss = 0.f;
    for (int j = threadIdx.x; j < INPD; j += 256) {
        float v = xr[j];
        s += v; ss += v * v;
    }
    __shared__ float sh[256], sh2[256];
    sh[threadIdx.x] = s; sh2[threadIdx.x] = ss;
    __syncthreads();
    for (int o = 128; o > 0; o >>= 1) {
        if (threadIdx.x < o) {
            sh[threadIdx.x]  += sh[threadIdx.x + o];
            sh2[threadIdx.x] += sh2[threadIdx.x + o];
        }
        __syncthreads();
    }
    if (threadIdx.x == 0) {
        float m = sh[0] / (float)INPD;
        float var = sh2[0] / (float)INPD - m * m;
        g_mean[row] = m;
        g_rstd[row] = rsqrtf(var + LN_EPS);
    }
}

// ---------------------------------------------------------------------------
// Generic tiled SGEMM: C[M,N] = ep(A' @ B + bias), 64x64x16 tile, 256 threads,
// 4x4 per-thread microtile.
//   A' = A, or LN(A) row-wise using g_mean/g_rstd + (lnG, lnB) if useLN.
//   B layout: bTrans==0 -> B[k*N+n] ;  bTrans==1 -> B[n*K+k]  (i.e. A@B^T)
//   epilogue: +bias[col] (if bias), relu (if doRelu), +resid[row,col] (if resid)
//   (relu applied BEFORE residual add: matches h + relu(...))
// All of M, N divisible by 64; K divisible by 16 (holds for every call here).
// ---------------------------------------------------------------------------
__global__ void sgemm_kernel(const float* __restrict__ A,
                             const float* __restrict__ B,
                             const float* __restrict__ bias,
                             float* __restrict__ C,
                             const float* __restrict__ resid,
                             int N, int K,
                             int bTrans, int doRelu,
                             const float* __restrict__ lnG,
                             const float* __restrict__ lnB,
                             int useLN)
{
    __shared__ float As[16][64];
    __shared__ float Bs[16][64];

    int tid = threadIdx.x;          // 0..255
    int tx = tid & 15, ty = tid >> 4;
    int bx = blockIdx.x, by = blockIdx.y;

    // A-tile loader mapping: 64 rows x 16 cols, float4 per thread
    int ar = tid >> 2;              // 0..63
    int ac = (tid & 3) << 2;        // 0,4,8,12
    // B-tile loader (non-trans): 16 rows x 64 cols
    int brow = tid >> 4;            // 0..15
    int bcol = (tid & 15) << 2;     // 0..60

    const float* Arow = A + (size_t)(by * 64 + ar) * K + ac;
    float lm = 0.f, lr = 0.f;
    if (useLN) {
        lm = g_mean[by * 64 + ar];
        lr = g_rstd[by * 64 + ar];
    }

    float acc[4][4];
#pragma unroll
    for (int i = 0; i < 4; i++)
#pragma unroll
        for (int j = 0; j < 4; j++) acc[i][j] = 0.f;

    for (int kt = 0; kt < K; kt += 16) {
        float4 av = *(const float4*)(Arow + kt);
        if (useLN) {
            int kg = kt + ac;
            av.x = (av.x - lm) * lr * lnG[kg + 0] + lnB[kg + 0];
            av.y = (av.y - lm) * lr * lnG[kg + 1] + lnB[kg + 1];
            av.z = (av.z - lm) * lr * lnG[kg + 2] + lnB[kg + 2];
            av.w = (av.w - lm) * lr * lnG[kg + 3] + lnB[kg + 3];
        }
        As[ac + 0][ar] = av.x;
        As[ac + 1][ar] = av.y;
        As[ac + 2][ar] = av.z;
        As[ac + 3][ar] = av.w;

        if (!bTrans) {
            float4 bv = *(const float4*)(B + (size_t)(kt + brow) * N + bx * 64 + bcol);
            *(float4*)&Bs[brow][bcol] = bv;
        } else {
            int bn = tid >> 2;            // 0..63
            int bk = (tid & 3) << 2;      // 0,4,8,12
            float4 bv = *(const float4*)(B + (size_t)(bx * 64 + bn) * K + kt + bk);
            Bs[bk + 0][bn] = bv.x;
            Bs[bk + 1][bn] = bv.y;
            Bs[bk + 2][bn] = bv.z;
            Bs[bk + 3][bn] = bv.w;
        }
        __syncthreads();

#pragma unroll
        for (int k = 0; k < 16; k++) {
            float4 a = *(const float4*)&As[k][ty << 2];
            float4 b = *(const float4*)&Bs[k][tx << 2];
            acc[0][0] += a.x * b.x; acc[0][1] += a.x * b.y;
            acc[0][2] += a.x * b.z; acc[0][3] += a.x * b.w;
            acc[1][0] += a.y * b.x; acc[1][1] += a.y * b.y;
            acc[1][2] += a.y * b.z; acc[1][3] += a.y * b.w;
            acc[2][0] += a.z * b.x; acc[2][1] += a.z * b.y;
            acc[2][2] += a.z * b.z; acc[2][3] += a.z * b.w;
            acc[3][0] += a.w * b.x; acc[3][1] += a.w * b.y;
            acc[3][2] += a.w * b.z; acc[3][3] += a.w * b.w;
        }
        __syncthreads();
    }

#pragma unroll
    for (int i = 0; i < 4; i++) {
        int row = by * 64 + (ty << 2) + i;
#pragma unroll
        for (int j = 0; j < 4; j++) {
            int col = bx * 64 + (tx << 2) + j;
            float v = acc[i][j];
            if (bias) v += bias[col];
            if (doRelu) v = fmaxf(v, 0.f);
            if (resid) v += resid[(size_t)row * N + col];
            C[(size_t)row * N + col] = v;
        }
    }
}

// ---------------------------------------------------------------------------
// LN over 768 + write pred_y + L2-normalize into g_PN. One block per row.
// ---------------------------------------------------------------------------
__global__ void ln2_norm_kernel(const float* __restrict__ P,
                                const float* __restrict__ g,
                                const float* __restrict__ b,
                                float* __restrict__ pred)
{
    int row = blockIdx.x;
    int tid = threadIdx.x;
    const float* pr = P + (size_t)row * OUTD;

    float v[3];
    float s = 0.f, ss = 0.f;
#pragma unroll
    for (int i = 0; i < 3; i++) {
        int j = tid + i * 256;
        v[i] = pr[j];
        s += v[i]; ss += v[i] * v[i];
    }
    __shared__ float sh[256], sh2[256];
    sh[tid] = s; sh2[tid] = ss;
    __syncthreads();
    for (int o = 128; o > 0; o >>= 1) {
        if (tid < o) { sh[tid] += sh[tid + o]; sh2[tid] += sh2[tid + o]; }
        __syncthreads();
    }
    __shared__ float smean, srstd;
    if (tid == 0) {
        float m = sh[0] / (float)OUTD;
        float var = sh2[0] / (float)OUTD - m * m;
        smean = m;
        srstd = rsqrtf(var + LN_EPS);
    }
    __syncthreads();

    float t[3];
    float tss = 0.f;
#pragma unroll
    for (int i = 0; i < 3; i++) {
        int j = tid + i * 256;
        t[i] = (v[i] - smean) * srstd * g[j] + b[j];
        tss += t[i] * t[i];
    }
    __syncthreads();
    sh[tid] = tss;
    __syncthreads();
    for (int o = 128; o > 0; o >>= 1) {
        if (tid < o) sh[tid] += sh[tid + o];
        __syncthreads();
    }
    __shared__ float sinv;
    if (tid == 0) sinv = 1.f / sqrtf(sh[0]);
    __syncthreads();

    float* pw  = pred + (size_t)row * OUTD;
    float* pnw = g_PN + (size_t)row * OUTD;
#pragma unroll
    for (int i = 0; i < 3; i++) {
        int j = tid + i * 256;
        pw[j]  = t[i];
        pnw[j] = t[i] * sinv;
    }
}

// L2-normalize y rows into g_YN. One block per row.
__global__ void ynorm_kernel(const float* __restrict__ y)
{
    int row = blockIdx.x;
    int tid = threadIdx.x;
    const float* yr = y + (size_t)row * OUTD;
    float v[3];
    float ss = 0.f;
#pragma unroll
    for (int i = 0; i < 3; i++) {
        int j = tid + i * 256;
        v[i] = yr[j];
        ss += v[i] * v[i];
    }
    __shared__ float sh[256];
    sh[tid] = ss;
    __syncthreads();
    for (int o = 128; o > 0; o >>= 1) {
        if (tid < o) sh[tid] += sh[tid + o];
        __syncthreads();
    }
    __shared__ float sinv;
    if (tid == 0) sinv = 1.f / sqrtf(sh[0]);
    __syncthreads();
    float* w = g_YN + (size_t)row * OUTD;
#pragma unroll
    for (int i = 0; i < 3; i++) {
        int j = tid + i * 256;
        w[j] = v[i] * sinv;
    }
}

// ---------------------------------------------------------------------------
// Per-row of S: first-occurrence argmax + logsumexp; accumulate loss & acc.
// ---------------------------------------------------------------------------
__global__ void reduce_S_kernel()
{
    int row = blockIdx.x;
    int tid = threadIdx.x;
    const float* sr = g_S + (size_t)row * BSZ;

    float best = -3.4e38f;
    int bidx = 0x7fffffff;
    for (int j = tid; j < BSZ; j += 256) {
        float v = sr[j];
        if (v > best || (v == best && j < bidx)) { best = v; bidx = j; }
    }
    __shared__ float shv[256];
    __shared__ int   shi[256];
    shv[tid] = best; shi[tid] = bidx;
    __syncthreads();
    for (int o = 128; o > 0; o >>= 1) {
        if (tid < o) {
            float vo = shv[tid + o]; int io = shi[tid + o];
            if (vo > shv[tid] || (vo == shv[tid] && io < shi[tid])) {
                shv[tid] = vo; shi[tid] = io;
            }
        }
        __syncthreads();
    }
    __shared__ float smax;
    __shared__ int   samax;
    if (tid == 0) { smax = shv[0]; samax = shi[0]; }
    __syncthreads();

    float se = 0.f;
    for (int j = tid; j < BSZ; j += 256) se += expf(sr[j] - smax);
    shv[tid] = se;
    __syncthreads();
    for (int o = 128; o > 0; o >>= 1) {
        if (tid < o) shv[tid] += shv[tid + o];
        __syncthreads();
    }
    if (tid == 0) {
        float lse = smax + logf(shv[0]);
        double contrib = (double)lse - (double)sr[row];   // lse_i - S_ii
        atomicAdd(&g_loss, contrib);
        if (samax == row) atomicAdd(&g_correct, 1);
    }
}

__global__ void finalize_kernel(float* __restrict__ out, int out_size)
{
    const int NP = BSZ * OUTD;
    if (out_size >= NP + 2) {
        out[NP]     = (float)g_loss;
        out[NP + 1] = (float)g_correct / (float)BSZ;
    }
}

// ---------------------------------------------------------------------------
extern "C" void kernel_launch(void* const* d_in, const int* in_sizes, int n_in,
                              void* d_out, int out_size)
{
    const float* inp  = (const float*)d_in[0];
    const float* y    = (const float*)d_in[1];
    const float* ln1g = (const float*)d_in[2];
    const float* ln1b = (const float*)d_in[3];
    const float* W1   = (const float*)d_in[4];
    const float* b1   = (const float*)d_in[5];
    const float* Wa   = (const float*)d_in[6];
    const float* ba   = (const float*)d_in[7];
    const float* Wb   = (const float*)d_in[8];
    const float* bb   = (const float*)d_in[9];
    const float* W2   = (const float*)d_in[10];
    const float* b2   = (const float*)d_in[11];
    const float* ln2g = (const float*)d_in[12];
    const float* ln2b = (const float*)d_in[13];
    float* out = (float*)d_out;

    float *H, *T, *P, *S;
    cudaGetSymbolAddress((void**)&H, g_H);
    cudaGetSymbolAddress((void**)&T, g_T);
    cudaGetSymbolAddress((void**)&P, g_P);
    cudaGetSymbolAddress((void**)&S, g_S);
    float *PN, *YN;
    cudaGetSymbolAddress((void**)&PN, g_PN);
    cudaGetSymbolAddress((void**)&YN, g_YN);

    zero_accum_kernel<<<1, 1>>>();
    row_meanvar_kernel<<<BSZ, 256>>>(inp);

    // H = LN1(inp) @ W1 + b1        [8192,1024], K=3072 (LN fused into A-load)
    sgemm_kernel<<<dim3(HIDD / 64, BSZ / 64), 256>>>(
        inp, W1, b1, H, nullptr, HIDD, INPD, 0, 0, ln1g, ln1b, 1);

    // Two residual blocks with shared weights:
    // T = relu(H @ Wa + ba) ; H = H + relu(T @ Wb + bb)
    for (int r = 0; r < 2; r++) {
        sgemm_kernel<<<dim3(HIDD / 64, BSZ / 64), 256>>>(
            H, Wa, ba, T, nullptr, HIDD, HIDD, 0, 1, nullptr, nullptr, 0);
        sgemm_kernel<<<dim3(HIDD / 64, BSZ / 64), 256>>>(
            T, Wb, bb, H, H, HIDD, HIDD, 0, 1, nullptr, nullptr, 0);
    }

    // P = H @ W2 + b2               [8192,768], K=1024
    sgemm_kernel<<<dim3(OUTD / 64, BSZ / 64), 256>>>(
        H, W2, b2, P, nullptr, OUTD, HIDD, 0, 0, nullptr, nullptr, 0);

    // pred_y = LN2(P); PN = pred_y / ||pred_y|| ; YN = y / ||y||
    ln2_norm_kernel<<<BSZ, 256>>>(P, ln2g, ln2b, out);
    ynorm_kernel<<<BSZ, 256>>>(y);

    // S = PN @ YN^T                 [8192,8192], K=768
    sgemm_kernel<<<dim3(BSZ / 64, BSZ / 64), 256>>>(
        PN, YN, nullptr, S, nullptr, BSZ, OUTD, 1, 0, nullptr, nullptr, 0);

    reduce_S_kernel<<<BSZ, 256>>>();
    finalize_kernel<<<1, 1>>>(out, out_size);
}

// round 2
// speedup vs baseline: 1.2913x; 1.2913x over previous
#include <cuda_runtime.h>
#include <math.h>

#define BSZ  8192
#define INPD 3072
#define HIDD 1024
#define OUTD 768
#define LN_EPS 1e-5f

// ---------------------------------------------------------------------------
// Scratch (__device__ globals; no allocation allowed).
// ---------------------------------------------------------------------------
__device__ float g_mean[BSZ];
__device__ float g_rstd[BSZ];
__device__ float g_H[(size_t)BSZ * HIDD];
__device__ float g_T[(size_t)BSZ * HIDD];
__device__ float g_P[(size_t)BSZ * OUTD];
__device__ float g_PN[(size_t)BSZ * OUTD];
__device__ float g_YN[(size_t)BSZ * OUTD];
__device__ float g_S[(size_t)BSZ * BSZ];
__device__ double g_loss;
__device__ int    g_correct;

__global__ void zero_accum_kernel() {
    g_loss = 0.0;
    g_correct = 0;
}

__global__ void row_meanvar_kernel(const float* __restrict__ x) {
    int row = blockIdx.x;
    const float* xr = x + (size_t)row * INPD;
    float s = 0.f, ss = 0.f;
    for (int j = threadIdx.x; j < INPD; j += 256) {
        float v = xr[j];
        s += v; ss += v * v;
    }
    __shared__ float sh[256], sh2[256];
    sh[threadIdx.x] = s; sh2[threadIdx.x] = ss;
    __syncthreads();
    for (int o = 128; o > 0; o >>= 1) {
        if (threadIdx.x < o) {
            sh[threadIdx.x]  += sh[threadIdx.x + o];
            sh2[threadIdx.x] += sh2[threadIdx.x + o];
        }
        __syncthreads();
    }
    if (threadIdx.x == 0) {
        float m = sh[0] / (float)INPD;
        float var = sh2[0] / (float)INPD - m * m;
        g_mean[row] = m;
        g_rstd[row] = rsqrtf(var + LN_EPS);
    }
}

// ---------------------------------------------------------------------------
// 128x128x8 SGEMM, 256 threads, 8x8 microtile (split 4+4), double-buffered.
//   A' = A or LN(A) rowwise (g_mean/g_rstd + lnG/lnB) if useLN.
//   bTrans==0: B[k*N+n];  bTrans==1: B[n*K+k] (A@B^T).
//   epilogue: +bias[col], relu, +resid (relu BEFORE residual add).
// Requires M%128==0, N%128==0, K%8==0 (true for all calls).
// ---------------------------------------------------------------------------
__global__ void __launch_bounds__(256, 2)
sgemm_kernel(const float* __restrict__ A,
             const float* __restrict__ B,
             const float* __restrict__ bias,
             float* __restrict__ C,
             const float* __restrict__ resid,
             int N, int K,
             int bTrans, int doRelu,
             const float* __restrict__ lnG,
             const float* __restrict__ lnB,
             int useLN)
{
    __shared__ float As[2][8][128];
    __shared__ float Bs[2][8][128];

    const int tid = threadIdx.x;        // 0..255
    const int tx = tid & 15;            // n-group 0..15
    const int ty = tid >> 4;            // m-group 0..15
    const int bx = blockIdx.x, by = blockIdx.y;

    // A loader: row = tid>>1 (0..127), col = (tid&1)*4
    const int arow = tid >> 1;
    const int acol = (tid & 1) << 2;
    const float* Aptr = A + (size_t)(by * 128 + arow) * K + acol;
    float lm = 0.f, lr = 0.f;
    if (useLN) { lm = g_mean[by * 128 + arow]; lr = g_rstd[by * 128 + arow]; }

    // B loader (non-trans): row = tid>>5 (0..7), col = (tid&31)*4
    const int brow = tid >> 5;
    const int bcol = (tid & 31) << 2;
    // B loader (trans): n = tid>>1 (0..127), k = (tid&1)*4
    const int tbn = tid >> 1;
    const int tbk = (tid & 1) << 2;

    float acc[8][8];
#pragma unroll
    for (int i = 0; i < 8; i++)
#pragma unroll
        for (int j = 0; j < 8; j++) acc[i][j] = 0.f;

    const int ntiles = K >> 3;

    // ---- load tile 0 into buffer 0 ----
    {
        float4 av = *(const float4*)(Aptr);
        if (useLN) {
            av.x = (av.x - lm) * lr * lnG[acol + 0] + lnB[acol + 0];
            av.y = (av.y - lm) * lr * lnG[acol + 1] + lnB[acol + 1];
            av.z = (av.z - lm) * lr * lnG[acol + 2] + lnB[acol + 2];
            av.w = (av.w - lm) * lr * lnG[acol + 3] + lnB[acol + 3];
        }
        As[0][acol + 0][arow] = av.x;
        As[0][acol + 1][arow] = av.y;
        As[0][acol + 2][arow] = av.z;
        As[0][acol + 3][arow] = av.w;
        if (!bTrans) {
            float4 bv = *(const float4*)(B + (size_t)brow * N + bx * 128 + bcol);
            *(float4*)&Bs[0][brow][bcol] = bv;
        } else {
            float4 bv = *(const float4*)(B + (size_t)(bx * 128 + tbn) * K + tbk);
            Bs[0][tbk + 0][tbn] = bv.x;
            Bs[0][tbk + 1][tbn] = bv.y;
            Bs[0][tbk + 2][tbn] = bv.z;
            Bs[0][tbk + 3][tbn] = bv.w;
        }
    }
    __syncthreads();

    int buf = 0;
    for (int kt = 0; kt < ntiles; kt++) {
        float4 av, bv;
        const bool hasNext = (kt + 1) < ntiles;
        if (hasNext) {
            int kg = (kt + 1) << 3;
            av = *(const float4*)(Aptr + kg);
            if (useLN) {
                int c = kg + acol;
                av.x = (av.x - lm) * lr * lnG[c + 0] + lnB[c + 0];
                av.y = (av.y - lm) * lr * lnG[c + 1] + lnB[c + 1];
                av.z = (av.z - lm) * lr * lnG[c + 2] + lnB[c + 2];
                av.w = (av.w - lm) * lr * lnG[c + 3] + lnB[c + 3];
            }
            if (!bTrans)
                bv = *(const float4*)(B + (size_t)(kg + brow) * N + bx * 128 + bcol);
            else
                bv = *(const float4*)(B + (size_t)(bx * 128 + tbn) * K + kg + tbk);
        }

#pragma unroll
        for (int k = 0; k < 8; k++) {
            float4 a0 = *(const float4*)&As[buf][k][ty << 2];
            float4 a1 = *(const float4*)&As[buf][k][(ty << 2) + 64];
            float4 b0 = *(const float4*)&Bs[buf][k][tx << 2];
            float4 b1 = *(const float4*)&Bs[buf][k][(tx << 2) + 64];
            float am[8] = {a0.x, a0.y, a0.z, a0.w, a1.x, a1.y, a1.z, a1.w};
            float bn[8] = {b0.x, b0.y, b0.z, b0.w, b1.x, b1.y, b1.z, b1.w};
#pragma unroll
            for (int i = 0; i < 8; i++)
#pragma unroll
                for (int j = 0; j < 8; j++)
                    acc[i][j] += am[i] * bn[j];
        }

        if (hasNext) {
            int nb = buf ^ 1;
            As[nb][acol + 0][arow] = av.x;
            As[nb][acol + 1][arow] = av.y;
            As[nb][acol + 2][arow] = av.z;
            As[nb][acol + 3][arow] = av.w;
            if (!bTrans) {
                *(float4*)&Bs[nb][brow][bcol] = bv;
            } else {
                Bs[nb][tbk + 0][tbn] = bv.x;
                Bs[nb][tbk + 1][tbn] = bv.y;
                Bs[nb][tbk + 2][tbn] = bv.z;
                Bs[nb][tbk + 3][tbn] = bv.w;
            }
            __syncthreads();
            buf = nb;
        }
    }

    // ---- epilogue ----
#pragma unroll
    for (int i = 0; i < 8; i++) {
        int row = by * 128 + (ty << 2) + (i & 3) + ((i >= 4) ? 64 : 0);
#pragma unroll
        for (int jh = 0; jh < 2; jh++) {
            int col = bx * 128 + (tx << 2) + jh * 64;
            float4 v;
            v.x = acc[i][jh * 4 + 0];
            v.y = acc[i][jh * 4 + 1];
            v.z = acc[i][jh * 4 + 2];
            v.w = acc[i][jh * 4 + 3];
            if (bias) {
                v.x += bias[col + 0]; v.y += bias[col + 1];
                v.z += bias[col + 2]; v.w += bias[col + 3];
            }
            if (doRelu) {
                v.x = fmaxf(v.x, 0.f); v.y = fmaxf(v.y, 0.f);
                v.z = fmaxf(v.z, 0.f); v.w = fmaxf(v.w, 0.f);
            }
            if (resid) {
                float4 r = *(const float4*)(resid + (size_t)row * N + col);
                v.x += r.x; v.y += r.y; v.z += r.z; v.w += r.w;
            }
            *(float4*)(C + (size_t)row * N + col) = v;
        }
    }
}

// ---------------------------------------------------------------------------
__global__ void ln2_norm_kernel(const float* __restrict__ P,
                                const float* __restrict__ g,
                                const float* __restrict__ b,
                                float* __restrict__ pred)
{
    int row = blockIdx.x;
    int tid = threadIdx.x;
    const float* pr = P + (size_t)row * OUTD;

    float v[3];
    float s = 0.f, ss = 0.f;
#pragma unroll
    for (int i = 0; i < 3; i++) {
        int j = tid + i * 256;
        v[i] = pr[j];
        s += v[i]; ss += v[i] * v[i];
    }
    __shared__ float sh[256], sh2[256];
    sh[tid] = s; sh2[tid] = ss;
    __syncthreads();
    for (int o = 128; o > 0; o >>= 1) {
        if (tid < o) { sh[tid] += sh[tid + o]; sh2[tid] += sh2[tid + o]; }
        __syncthreads();
    }
    __shared__ float smean, srstd;
    if (tid == 0) {
        float m = sh[0] / (float)OUTD;
        float var = sh2[0] / (float)OUTD - m * m;
        smean = m;
        srstd = rsqrtf(var + LN_EPS);
    }
    __syncthreads();

    float t[3];
    float tss = 0.f;
#pragma unroll
    for (int i = 0; i < 3; i++) {
        int j = tid + i * 256;
        t[i] = (v[i] - smean) * srstd * g[j] + b[j];
        tss += t[i] * t[i];
    }
    __syncthreads();
    sh[tid] = tss;
    __syncthreads();
    for (int o = 128; o > 0; o >>= 1) {
        if (tid < o) sh[tid] += sh[tid + o];
        __syncthreads();
    }
    __shared__ float sinv;
    if (tid == 0) sinv = 1.f / sqrtf(sh[0]);
    __syncthreads();

    float* pw  = pred + (size_t)row * OUTD;
    float* pnw = g_PN + (size_t)row * OUTD;
#pragma unroll
    for (int i = 0; i < 3; i++) {
        int j = tid + i * 256;
        pw[j]  = t[i];
        pnw[j] = t[i] * sinv;
    }
}

__global__ void ynorm_kernel(const float* __restrict__ y)
{
    int row = blockIdx.x;
    int tid = threadIdx.x;
    const float* yr = y + (size_t)row * OUTD;
    float v[3];
    float ss = 0.f;
#pragma unroll
    for (int i = 0; i < 3; i++) {
        int j = tid + i * 256;
        v[i] = yr[j];
        ss += v[i] * v[i];
    }
    __shared__ float sh[256];
    sh[tid] = ss;
    __syncthreads();
    for (int o = 128; o > 0; o >>= 1) {
        if (tid < o) sh[tid] += sh[tid + o];
        __syncthreads();
    }
    __shared__ float sinv;
    if (tid == 0) sinv = 1.f / sqrtf(sh[0]);
    __syncthreads();
    float* w = g_YN + (size_t)row * OUTD;
#pragma unroll
    for (int i = 0; i < 3; i++) {
        int j = tid + i * 256;
        w[j] = v[i] * sinv;
    }
}

// ---------------------------------------------------------------------------
__global__ void reduce_S_kernel()
{
    int row = blockIdx.x;
    int tid = threadIdx.x;
    const float* sr = g_S + (size_t)row * BSZ;

    float best = -3.4e38f;
    int bidx = 0x7fffffff;
    for (int j = tid; j < BSZ; j += 256) {
        float v = sr[j];
        if (v > best || (v == best && j < bidx)) { best = v; bidx = j; }
    }
    __shared__ float shv[256];
    __shared__ int   shi[256];
    shv[tid] = best; shi[tid] = bidx;
    __syncthreads();
    for (int o = 128; o > 0; o >>= 1) {
        if (tid < o) {
            float vo = shv[tid + o]; int io = shi[tid + o];
            if (vo > shv[tid] || (vo == shv[tid] && io < shi[tid])) {
                shv[tid] = vo; shi[tid] = io;
            }
        }
        __syncthreads();
    }
    __shared__ float smax;
    __shared__ int   samax;
    if (tid == 0) { smax = shv[0]; samax = shi[0]; }
    __syncthreads();

    float se = 0.f;
    for (int j = tid; j < BSZ; j += 256) se += __expf(sr[j] - smax);
    shv[tid] = se;
    __syncthreads();
    for (int o = 128; o > 0; o >>= 1) {
        if (tid < o) shv[tid] += shv[tid + o];
        __syncthreads();
    }
    if (tid == 0) {
        float lse = smax + __logf(shv[0]);
        double contrib = (double)lse - (double)sr[row];
        atomicAdd(&g_loss, contrib);
        if (samax == row) atomicAdd(&g_correct, 1);
    }
}

__global__ void finalize_kernel(float* __restrict__ out, int out_size)
{
    const int NP = BSZ * OUTD;
    if (out_size >= NP + 2) {
        out[NP]     = (float)g_loss;
        out[NP + 1] = (float)g_correct / (float)BSZ;
    }
}

// ---------------------------------------------------------------------------
extern "C" void kernel_launch(void* const* d_in, const int* in_sizes, int n_in,
                              void* d_out, int out_size)
{
    const float* inp  = (const float*)d_in[0];
    const float* y    = (const float*)d_in[1];
    const float* ln1g = (const float*)d_in[2];
    const float* ln1b = (const float*)d_in[3];
    const float* W1   = (const float*)d_in[4];
    const float* b1   = (const float*)d_in[5];
    const float* Wa   = (const float*)d_in[6];
    const float* ba   = (const float*)d_in[7];
    const float* Wb   = (const float*)d_in[8];
    const float* bb   = (const float*)d_in[9];
    const float* W2   = (const float*)d_in[10];
    const float* b2   = (const float*)d_in[11];
    const float* ln2g = (const float*)d_in[12];
    const float* ln2b = (const float*)d_in[13];
    float* out = (float*)d_out;

    float *H, *T, *P, *S, *PN, *YN;
    cudaGetSymbolAddress((void**)&H, g_H);
    cudaGetSymbolAddress((void**)&T, g_T);
    cudaGetSymbolAddress((void**)&P, g_P);
    cudaGetSymbolAddress((void**)&S, g_S);
    cudaGetSymbolAddress((void**)&PN, g_PN);
    cudaGetSymbolAddress((void**)&YN, g_YN);

    zero_accum_kernel<<<1, 1>>>();
    row_meanvar_kernel<<<BSZ, 256>>>(inp);

    // H = LN1(inp) @ W1 + b1        [8192,1024], K=3072
    sgemm_kernel<<<dim3(HIDD / 128, BSZ / 128), 256>>>(
        inp, W1, b1, H, nullptr, HIDD, INPD, 0, 0, ln1g, ln1b, 1);

    // Two residual blocks (shared weights):
    for (int r = 0; r < 2; r++) {
        sgemm_kernel<<<dim3(HIDD / 128, BSZ / 128), 256>>>(
            H, Wa, ba, T, nullptr, HIDD, HIDD, 0, 1, nullptr, nullptr, 0);
        sgemm_kernel<<<dim3(HIDD / 128, BSZ / 128), 256>>>(
            T, Wb, bb, H, H, HIDD, HIDD, 0, 1, nullptr, nullptr, 0);
    }

    // P = H @ W2 + b2               [8192,768], K=1024
    sgemm_kernel<<<dim3(OUTD / 128, BSZ / 128), 256>>>(
        H, W2, b2, P, nullptr, OUTD, HIDD, 0, 0, nullptr, nullptr, 0);

    // pred_y = LN2(P); PN, YN
    ln2_norm_kernel<<<BSZ, 256>>>(P, ln2g, ln2b, out);
    ynorm_kernel<<<BSZ, 256>>>(y);

    // S = PN @ YN^T                 [8192,8192], K=768
    sgemm_kernel<<<dim3(BSZ / 128, BSZ / 128), 256>>>(
        PN, YN, nullptr, S, nullptr, BSZ, OUTD, 1, 0, nullptr, nullptr, 0);

    reduce_S_kernel<<<BSZ, 256>>>();
    finalize_kernel<<<1, 1>>>(out, out_size);
}

// round 4
// speedup vs baseline: 1.9425x; 1.5043x over previous
#include <cuda_runtime.h>
#include <cuda_bf16.h>
#include <math.h>
#include <stdint.h>

#define BSZ  8192
#define INPD 3072
#define HIDD 1024
#define OUTD 768
#define LN_EPS 1e-5f

// ===========================================================================
// Scratch (__device__ globals; no allocations allowed anywhere).
// ===========================================================================
__device__ float g_H[(size_t)BSZ * HIDD];
__device__ float g_P[(size_t)BSZ * OUTD];
__device__ float g_S[(size_t)BSZ * BSZ];
__device__ double g_loss;
__device__ int    g_correct;

// bf16 hi/lo split operand buffers
__device__ __nv_bfloat16 g_A1h[(size_t)BSZ * INPD];
__device__ __nv_bfloat16 g_A1l[(size_t)BSZ * INPD];
__device__ __nv_bfloat16 g_Hh[(size_t)BSZ * HIDD];
__device__ __nv_bfloat16 g_Hl[(size_t)BSZ * HIDD];
__device__ __nv_bfloat16 g_Th[(size_t)BSZ * HIDD];
__device__ __nv_bfloat16 g_Tl[(size_t)BSZ * HIDD];
__device__ __nv_bfloat16 g_PNh[(size_t)BSZ * OUTD];
__device__ __nv_bfloat16 g_PNl[(size_t)BSZ * OUTD];
__device__ __nv_bfloat16 g_YNh[(size_t)BSZ * OUTD];
__device__ __nv_bfloat16 g_YNl[(size_t)BSZ * OUTD];
// transposed + split weights: layout [N rows][K cols], K-major
__device__ __nv_bfloat16 g_W1h[(size_t)HIDD * INPD];
__device__ __nv_bfloat16 g_W1l[(size_t)HIDD * INPD];
__device__ __nv_bfloat16 g_Wah[(size_t)HIDD * HIDD];
__device__ __nv_bfloat16 g_Wal[(size_t)HIDD * HIDD];
__device__ __nv_bfloat16 g_Wbh[(size_t)HIDD * HIDD];
__device__ __nv_bfloat16 g_Wbl[(size_t)HIDD * HIDD];
__device__ __nv_bfloat16 g_W2h[(size_t)OUTD * HIDD];
__device__ __nv_bfloat16 g_W2l[(size_t)OUTD * HIDD];

// ===========================================================================
// Helpers (base compute_103 features only: mma.sync / ldmatrix / cp.async)
// ===========================================================================
__device__ __forceinline__ uint32_t smem_to_u32(const void* p) {
    uint32_t a;
    asm("{ .reg .u64 t; cvta.to.shared.u64 t, %1; cvt.u32.u64 %0, t; }"
        : "=r"(a) : "l"(p));
    return a;
}

__device__ __forceinline__ void cp_async16(uint32_t saddr, const void* gaddr) {
    asm volatile("cp.async.cg.shared.global [%0], [%1], 16;"
                 :: "r"(saddr), "l"(gaddr) : "memory");
}
__device__ __forceinline__ void cp_commit() {
    asm volatile("cp.async.commit_group;" ::: "memory");
}
template <int N>
__device__ __forceinline__ void cp_wait() {
    asm volatile("cp.async.wait_group %0;" :: "n"(N) : "memory");
}

__device__ __forceinline__ void ldsm4(uint32_t* r, uint32_t addr) {
    asm volatile("ldmatrix.sync.aligned.m8n8.x4.shared.b16 {%0,%1,%2,%3}, [%4];"
                 : "=r"(r[0]), "=r"(r[1]), "=r"(r[2]), "=r"(r[3]) : "r"(addr));
}

__device__ __forceinline__ void mma16816(float* c, const uint32_t* a,
                                         uint32_t b0, uint32_t b1) {
    asm volatile(
        "mma.sync.aligned.m16n8k16.row.col.f32.bf16.bf16.f32 "
        "{%0,%1,%2,%3}, {%4,%5,%6,%7}, {%8,%9}, {%0,%1,%2,%3};"
        : "+f"(c[0]), "+f"(c[1]), "+f"(c[2]), "+f"(c[3])
        : "r"(a[0]), "r"(a[1]), "r"(a[2]), "r"(a[3]), "r"(b0), "r"(b1));
}

__device__ __forceinline__ void split_bf16(float v, __nv_bfloat16& h, __nv_bfloat16& l) {
    h = __float2bfloat16_rn(v);
    l = __float2bfloat16_rn(v - __bfloat162float(h));
}

// ===========================================================================
// Misc small kernels
// ===========================================================================
__global__ void zero_accum_kernel() { g_loss = 0.0; g_correct = 0; }

// Transpose W[K,N] -> (hi,lo) bf16 [N,K]
__global__ void tsplit_kernel(const float* __restrict__ W,
                              __nv_bfloat16* __restrict__ TH,
                              __nv_bfloat16* __restrict__ TL,
                              int K, int N)
{
    __shared__ float t[32][33];
    int k0 = blockIdx.x * 32, n0 = blockIdx.y * 32;
    int tx = threadIdx.x, ty = threadIdx.y;   // 32 x 8
#pragma unroll
    for (int i = 0; i < 32; i += 8)
        t[ty + i][tx] = W[(size_t)(k0 + ty + i) * N + n0 + tx];
    __syncthreads();
#pragma unroll
    for (int i = 0; i < 32; i += 8) {
        float v = t[tx][ty + i];
        __nv_bfloat16 h, l;
        split_bf16(v, h, l);
        size_t o = (size_t)(n0 + ty + i) * K + k0 + tx;
        TH[o] = h;
        TL[o] = l;
    }
}

// LN1 + split
__global__ void ln1_split_kernel(const float* __restrict__ x,
                                 const float* __restrict__ g,
                                 const float* __restrict__ b)
{
    int row = blockIdx.x, tid = threadIdx.x;
    const float* xr = x + (size_t)row * INPD;
    float v[12];
    float s = 0.f, ss = 0.f;
#pragma unroll
    for (int i = 0; i < 12; i++) {
        int j = tid + i * 256;
        v[i] = xr[j];
        s += v[i]; ss += v[i] * v[i];
    }
    __shared__ float sh[256], sh2[256];
    sh[tid] = s; sh2[tid] = ss;
    __syncthreads();
    for (int o = 128; o > 0; o >>= 1) {
        if (tid < o) { sh[tid] += sh[tid + o]; sh2[tid] += sh2[tid + o]; }
        __syncthreads();
    }
    __shared__ float sm, sr;
    if (tid == 0) {
        float m = sh[0] / (float)INPD;
        float var = sh2[0] / (float)INPD - m * m;
        sm = m; sr = rsqrtf(var + LN_EPS);
    }
    __syncthreads();
    float m = sm, r = sr;
#pragma unroll
    for (int i = 0; i < 12; i++) {
        int j = tid + i * 256;
        float t = (v[i] - m) * r * g[j] + b[j];
        __nv_bfloat16 h, l;
        split_bf16(t, h, l);
        size_t o = (size_t)row * INPD + j;
        g_A1h[o] = h; g_A1l[o] = l;
    }
}

// ===========================================================================
// Tensor-core GEMM via mma.sync: C[M,N] = ep(A @ B^T)
// A=[M,K] bf16 pair, B=[N,K] bf16 pair; bf16x3: hh + hl + lh, fp32 accum.
// Block tile 128x128, 8 warps (2x4), warp tile 64x32, k-chunk 32.
// Smem rows padded to 80B (40 bf16) -> conflict-free LDSM.
// ===========================================================================
#define SMS   80                 // smem row stride in bytes
#define BUF   10240              // one 128x32 bf16 buffer (128*80)
#define STAGE (4 * BUF)          // Ah, Al, Bh, Bl
#define GEMM_SMEM_BYTES (2 * STAGE)

__global__ void __launch_bounds__(256)
tc_gemm(const __nv_bfloat16* __restrict__ AHi, const __nv_bfloat16* __restrict__ ALo,
        const __nv_bfloat16* __restrict__ BHi, const __nv_bfloat16* __restrict__ BLo,
        const float* __restrict__ bias, const float* __restrict__ resid,
        float* __restrict__ C,
        __nv_bfloat16* __restrict__ CHi, __nv_bfloat16* __restrict__ CLo,
        int N, int K, int doRelu)
{
    extern __shared__ char smem[];
    const uint32_t sbase = smem_to_u32(smem);
    const int tid = threadIdx.x;
    const int wid = tid >> 5, lid = tid & 31;
    const int wm = wid & 1, wn = wid >> 1;     // 2 x 4 warp grid
    const int m0 = blockIdx.y * 128, n0 = blockIdx.x * 128;
    const size_t ldb = (size_t)K * 2;          // bytes per row

    const char* gAh = (const char*)AHi + (size_t)m0 * ldb;
    const char* gAl = (const char*)ALo + (size_t)m0 * ldb;
    const char* gBh = (const char*)BHi + (size_t)n0 * ldb;
    const char* gBl = (const char*)BLo + (size_t)n0 * ldb;

    // loader mapping: idx -> row(0..127), 16B chunk(0..3)
    const int l_row = tid >> 2;
    const int l_ch  = (tid & 3) << 4;          // byte offset within 64B
    const uint32_t l_soff = (uint32_t)l_row * SMS + l_ch;

    // ldmatrix lane offsets
    const uint32_t aOff = (uint32_t)((wm * 64 + (lid & 15)) * SMS) + ((lid >> 4) << 4);
    const uint32_t bOff = (uint32_t)((wn * 32 + (lid & 7) + ((lid >> 4) << 3)) * SMS)
                        + (((lid >> 3) & 1) << 4);

    float acc[4][4][4];
#pragma unroll
    for (int i = 0; i < 4; i++)
#pragma unroll
        for (int j = 0; j < 4; j++)
#pragma unroll
            for (int q = 0; q < 4; q++) acc[i][j][q] = 0.f;

    const int nch = K >> 5;                     // k-chunks of 32

    auto issue = [&](int kt) {
        const uint32_t st = sbase + (uint32_t)(kt & 1) * STAGE;
        const size_t kb = (size_t)kt * 64;      // 32 bf16 = 64 bytes
#pragma unroll
        for (int it = 0; it < 2; it++) {
            int row = l_row + it * 64;
            uint32_t so = l_soff + (uint32_t)it * 64 * SMS;
            size_t go = (size_t)row * ldb + kb + l_ch;
            cp_async16(st +           so, gAh + go);
            cp_async16(st + BUF     + so, gAl + go);
            cp_async16(st + 2 * BUF + so, gBh + go);
            cp_async16(st + 3 * BUF + so, gBl + go);
        }
        cp_commit();
    };

    issue(0);
    for (int kt = 0; kt < nch; kt++) {
        if (kt + 1 < nch) { issue(kt + 1); cp_wait<1>(); }
        else              { cp_wait<0>(); }
        __syncthreads();

        const uint32_t st = sbase + (uint32_t)(kt & 1) * STAGE;
#pragma unroll
        for (int kk = 0; kk < 2; kk++) {
            const uint32_t kkB = kk << 5;       // 16 bf16 = 32 bytes
            uint32_t bh[2][4], bl[2][4];
#pragma unroll
            for (int np = 0; np < 2; np++) {
                ldsm4(bh[np], st + 2 * BUF + bOff + (uint32_t)np * 16 * SMS + kkB);
                ldsm4(bl[np], st + 3 * BUF + bOff + (uint32_t)np * 16 * SMS + kkB);
            }
#pragma unroll
            for (int mi = 0; mi < 4; mi++) {
                uint32_t ah[4], al[4];
                ldsm4(ah, st +       aOff + (uint32_t)mi * 16 * SMS + kkB);
                ldsm4(al, st + BUF + aOff + (uint32_t)mi * 16 * SMS + kkB);
#pragma unroll
                for (int ni = 0; ni < 4; ni++) {
                    const int np = ni >> 1, hh = (ni & 1) << 1;
                    mma16816(acc[mi][ni], ah, bh[np][hh], bh[np][hh + 1]);
                    mma16816(acc[mi][ni], ah, bl[np][hh], bl[np][hh + 1]);
                    mma16816(acc[mi][ni], al, bh[np][hh], bh[np][hh + 1]);
                }
            }
        }
        __syncthreads();
    }

    // ---- epilogue ----
#pragma unroll
    for (int mi = 0; mi < 4; mi++) {
#pragma unroll
        for (int ni = 0; ni < 4; ni++) {
            const int col = n0 + wn * 32 + ni * 8 + ((lid & 3) << 1);
#pragma unroll
            for (int half = 0; half < 2; half++) {
                const int row = m0 + wm * 64 + mi * 16 + (lid >> 2) + half * 8;
                float v0 = acc[mi][ni][half * 2 + 0];
                float v1 = acc[mi][ni][half * 2 + 1];
                if (bias) { v0 += bias[col]; v1 += bias[col + 1]; }
                if (doRelu) { v0 = fmaxf(v0, 0.f); v1 = fmaxf(v1, 0.f); }
                if (resid) {
                    float2 r = *(const float2*)(resid + (size_t)row * N + col);
                    v0 += r.x; v1 += r.y;
                }
                if (C) {
                    float2 w; w.x = v0; w.y = v1;
                    *(float2*)(C + (size_t)row * N + col) = w;
                }
                if (CHi) {
                    __nv_bfloat16 h0, l0, h1, l1;
                    split_bf16(v0, h0, l0);
                    split_bf16(v1, h1, l1);
                    uint32_t ph = (uint32_t)__bfloat16_as_ushort(h0) |
                                  ((uint32_t)__bfloat16_as_ushort(h1) << 16);
                    uint32_t pl = (uint32_t)__bfloat16_as_ushort(l0) |
                                  ((uint32_t)__bfloat16_as_ushort(l1) << 16);
                    *(uint32_t*)(CHi + (size_t)row * N + col) = ph;
                    *(uint32_t*)(CLo + (size_t)row * N + col) = pl;
                }
            }
        }
    }
}

// ===========================================================================
// LN2 + normalize + split; write pred (f32) and PN pair.
// ===========================================================================
__global__ void ln2_norm_kernel(const float* __restrict__ P,
                                const float* __restrict__ g,
                                const float* __restrict__ b,
                                float* __restrict__ pred)
{
    int row = blockIdx.x, tid = threadIdx.x;
    const float* pr = P + (size_t)row * OUTD;
    float v[3];
    float s = 0.f, ss = 0.f;
#pragma unroll
    for (int i = 0; i < 3; i++) {
        int j = tid + i * 256;
        v[i] = pr[j];
        s += v[i]; ss += v[i] * v[i];
    }
    __shared__ float sh[256], sh2[256];
    sh[tid] = s; sh2[tid] = ss;
    __syncthreads();
    for (int o = 128; o > 0; o >>= 1) {
        if (tid < o) { sh[tid] += sh[tid + o]; sh2[tid] += sh2[tid + o]; }
        __syncthreads();
    }
    __shared__ float smean, srstd;
    if (tid == 0) {
        float m = sh[0] / (float)OUTD;
        float var = sh2[0] / (float)OUTD - m * m;
        smean = m; srstd = rsqrtf(var + LN_EPS);
    }
    __syncthreads();
    float t[3];
    float tss = 0.f;
#pragma unroll
    for (int i = 0; i < 3; i++) {
        int j = tid + i * 256;
        t[i] = (v[i] - smean) * srstd * g[j] + b[j];
        tss += t[i] * t[i];
    }
    __syncthreads();
    sh[tid] = tss;
    __syncthreads();
    for (int o = 128; o > 0; o >>= 1) {
        if (tid < o) sh[tid] += sh[tid + o];
        __syncthreads();
    }
    __shared__ float sinv;
    if (tid == 0) sinv = 1.f / sqrtf(sh[0]);
    __syncthreads();
    float* pw = pred + (size_t)row * OUTD;
#pragma unroll
    for (int i = 0; i < 3; i++) {
        int j = tid + i * 256;
        pw[j] = t[i];
        float pn = t[i] * sinv;
        __nv_bfloat16 h, l;
        split_bf16(pn, h, l);
        size_t o = (size_t)row * OUTD + j;
        g_PNh[o] = h; g_PNl[o] = l;
    }
}

__global__ void ynorm_kernel(const float* __restrict__ y)
{
    int row = blockIdx.x, tid = threadIdx.x;
    const float* yr = y + (size_t)row * OUTD;
    float v[3];
    float ss = 0.f;
#pragma unroll
    for (int i = 0; i < 3; i++) {
        int j = tid + i * 256;
        v[i] = yr[j];
        ss += v[i] * v[i];
    }
    __shared__ float sh[256];
    sh[tid] = ss;
    __syncthreads();
    for (int o = 128; o > 0; o >>= 1) {
        if (tid < o) sh[tid] += sh[tid + o];
        __syncthreads();
    }
    __shared__ float sinv;
    if (tid == 0) sinv = 1.f / sqrtf(sh[0]);
    __syncthreads();
#pragma unroll
    for (int i = 0; i < 3; i++) {
        int j = tid + i * 256;
        float yn = v[i] * sinv;
        __nv_bfloat16 h, l;
        split_bf16(yn, h, l);
        size_t o = (size_t)row * OUTD + j;
        g_YNh[o] = h; g_YNl[o] = l;
    }
}

// ===========================================================================
// Reduce S: per-row argmax (first occurrence) + logsumexp.
// ===========================================================================
__global__ void reduce_S_kernel()
{
    int row = blockIdx.x, tid = threadIdx.x;
    const float* sr = g_S + (size_t)row * BSZ;

    float best = -3.4e38f;
    int bidx = 0x7fffffff;
    for (int j = tid; j < BSZ; j += 256) {
        float v = sr[j];
        if (v > best || (v == best && j < bidx)) { best = v; bidx = j; }
    }
    __shared__ float shv[256];
    __shared__ int   shi[256];
    shv[tid] = best; shi[tid] = bidx;
    __syncthreads();
    for (int o = 128; o > 0; o >>= 1) {
        if (tid < o) {
            float vo = shv[tid + o]; int io = shi[tid + o];
            if (vo > shv[tid] || (vo == shv[tid] && io < shi[tid])) {
                shv[tid] = vo; shi[tid] = io;
            }
        }
        __syncthreads();
    }
    __shared__ float smax;
    __shared__ int   samax;
    if (tid == 0) { smax = shv[0]; samax = shi[0]; }
    __syncthreads();

    float se = 0.f;
    for (int j = tid; j < BSZ; j += 256) se += __expf(sr[j] - smax);
    shv[tid] = se;
    __syncthreads();
    for (int o = 128; o > 0; o >>= 1) {
        if (tid < o) shv[tid] += shv[tid + o];
        __syncthreads();
    }
    if (tid == 0) {
        float lse = smax + __logf(shv[0]);
        double contrib = (double)lse - (double)sr[row];
        atomicAdd(&g_loss, contrib);
        if (samax == row) atomicAdd(&g_correct, 1);
    }
}

__global__ void finalize_kernel(float* __restrict__ out, int out_size)
{
    const int NP = BSZ * OUTD;
    if (out_size >= NP + 2) {
        out[NP]     = (float)g_loss;
        out[NP + 1] = (float)g_correct / (float)BSZ;
    }
}

// ===========================================================================
extern "C" void kernel_launch(void* const* d_in, const int* in_sizes, int n_in,
                              void* d_out, int out_size)
{
    const float* inp  = (const float*)d_in[0];
    const float* y    = (const float*)d_in[1];
    const float* ln1g = (const float*)d_in[2];
    const float* ln1b = (const float*)d_in[3];
    const float* W1   = (const float*)d_in[4];
    const float* b1   = (const float*)d_in[5];
    const float* Wa   = (const float*)d_in[6];
    const float* ba   = (const float*)d_in[7];
    const float* Wb   = (const float*)d_in[8];
    const float* bb   = (const float*)d_in[9];
    const float* W2   = (const float*)d_in[10];
    const float* b2   = (const float*)d_in[11];
    const float* ln2g = (const float*)d_in[12];
    const float* ln2b = (const float*)d_in[13];
    float* out = (float*)d_out;

    static int smem_cfg_done = 0;
    if (!smem_cfg_done) {
        cudaFuncSetAttribute(tc_gemm, cudaFuncAttributeMaxDynamicSharedMemorySize,
                             GEMM_SMEM_BYTES);
        smem_cfg_done = 1;
    }

    float *H, *P, *S;
    cudaGetSymbolAddress((void**)&H, g_H);
    cudaGetSymbolAddress((void**)&P, g_P);
    cudaGetSymbolAddress((void**)&S, g_S);
    __nv_bfloat16 *A1h, *A1l, *Hh, *Hl, *Th, *Tl, *PNh, *PNl, *YNh, *YNl;
    __nv_bfloat16 *W1h, *W1l, *Wah, *Wal, *Wbh, *Wbl, *W2h, *W2l;
    cudaGetSymbolAddress((void**)&A1h, g_A1h);
    cudaGetSymbolAddress((void**)&A1l, g_A1l);
    cudaGetSymbolAddress((void**)&Hh,  g_Hh);
    cudaGetSymbolAddress((void**)&Hl,  g_Hl);
    cudaGetSymbolAddress((void**)&Th,  g_Th);
    cudaGetSymbolAddress((void**)&Tl,  g_Tl);
    cudaGetSymbolAddress((void**)&PNh, g_PNh);
    cudaGetSymbolAddress((void**)&PNl, g_PNl);
    cudaGetSymbolAddress((void**)&YNh, g_YNh);
    cudaGetSymbolAddress((void**)&YNl, g_YNl);
    cudaGetSymbolAddress((void**)&W1h, g_W1h);
    cudaGetSymbolAddress((void**)&W1l, g_W1l);
    cudaGetSymbolAddress((void**)&Wah, g_Wah);
    cudaGetSymbolAddress((void**)&Wal, g_Wal);
    cudaGetSymbolAddress((void**)&Wbh, g_Wbh);
    cudaGetSymbolAddress((void**)&Wbl, g_Wbl);
    cudaGetSymbolAddress((void**)&W2h, g_W2h);
    cudaGetSymbolAddress((void**)&W2l, g_W2l);

    zero_accum_kernel<<<1, 1>>>();

    // Weight transpose + bf16 split
    dim3 tb(32, 8);
    tsplit_kernel<<<dim3(INPD / 32, HIDD / 32), tb>>>(W1, W1h, W1l, INPD, HIDD);
    tsplit_kernel<<<dim3(HIDD / 32, HIDD / 32), tb>>>(Wa, Wah, Wal, HIDD, HIDD);
    tsplit_kernel<<<dim3(HIDD / 32, HIDD / 32), tb>>>(Wb, Wbh, Wbl, HIDD, HIDD);
    tsplit_kernel<<<dim3(HIDD / 32, OUTD / 32), tb>>>(W2, W2h, W2l, HIDD, OUTD);

    // LN1 + split input
    ln1_split_kernel<<<BSZ, 256>>>(inp, ln1g, ln1b);

    // H = LN1(inp) @ W1 + b1   [8192,1024] K=3072 -> f32 H + pair
    tc_gemm<<<dim3(HIDD / 128, BSZ / 128), 256, GEMM_SMEM_BYTES>>>(
        A1h, A1l, W1h, W1l, b1, nullptr, H, Hh, Hl, HIDD, INPD, 0);

    // Residual blocks (shared weights), x2
    for (int r = 0; r < 2; r++) {
        tc_gemm<<<dim3(HIDD / 128, BSZ / 128), 256, GEMM_SMEM_BYTES>>>(
            Hh, Hl, Wah, Wal, ba, nullptr, nullptr, Th, Tl, HIDD, HIDD, 1);
        tc_gemm<<<dim3(HIDD / 128, BSZ / 128), 256, GEMM_SMEM_BYTES>>>(
            Th, Tl, Wbh, Wbl, bb, H, H, Hh, Hl, HIDD, HIDD, 1);
    }

    // P = H @ W2 + b2   [8192,768] K=1024 -> f32 only
    tc_gemm<<<dim3(OUTD / 128, BSZ / 128), 256, GEMM_SMEM_BYTES>>>(
        Hh, Hl, W2h, W2l, b2, nullptr, P, nullptr, nullptr, OUTD, HIDD, 0);

    // pred = LN2(P); PN pair; YN pair
    ln2_norm_kernel<<<BSZ, 256>>>(P, ln2g, ln2b, out);
    ynorm_kernel<<<BSZ, 256>>>(y);

    // S = PN @ YN^T   [8192,8192] K=768 -> f32
    tc_gemm<<<dim3(BSZ / 128, BSZ / 128), 256, GEMM_SMEM_BYTES>>>(
        PNh, PNl, YNh, YNl, nullptr, nullptr, S, nullptr, nullptr, BSZ, OUTD, 0);

    reduce_S_kernel<<<BSZ, 256>>>();
    finalize_kernel<<<1, 1>>>(out, out_size);
}

// round 5
// speedup vs baseline: 2.3483x; 1.2089x over previous
#include <cuda_runtime.h>
#include <cuda_bf16.h>
#include <math.h>
#include <stdint.h>

#define BSZ  8192
#define INPD 3072
#define HIDD 1024
#define OUTD 768
#define LN_EPS 1e-5f

// ===========================================================================
// Scratch (__device__ globals; no allocations allowed anywhere).
// ===========================================================================
__device__ float g_H[(size_t)BSZ * HIDD];
__device__ float g_P[(size_t)BSZ * OUTD];
__device__ float g_S[(size_t)BSZ * BSZ];
__device__ double g_loss;
__device__ int    g_correct;

// bf16 hi/lo split operand buffers
__device__ __nv_bfloat16 g_A1h[(size_t)BSZ * INPD];
__device__ __nv_bfloat16 g_A1l[(size_t)BSZ * INPD];
__device__ __nv_bfloat16 g_Hh[(size_t)BSZ * HIDD];
__device__ __nv_bfloat16 g_Hl[(size_t)BSZ * HIDD];
__device__ __nv_bfloat16 g_Th[(size_t)BSZ * HIDD];
__device__ __nv_bfloat16 g_Tl[(size_t)BSZ * HIDD];
__device__ __nv_bfloat16 g_PNh[(size_t)BSZ * OUTD];
__device__ __nv_bfloat16 g_PNl[(size_t)BSZ * OUTD];
__device__ __nv_bfloat16 g_YNh[(size_t)BSZ * OUTD];
__device__ __nv_bfloat16 g_YNl[(size_t)BSZ * OUTD];
// transposed + split weights: layout [N rows][K cols], K-major
__device__ __nv_bfloat16 g_W1h[(size_t)HIDD * INPD];
__device__ __nv_bfloat16 g_W1l[(size_t)HIDD * INPD];
__device__ __nv_bfloat16 g_Wah[(size_t)HIDD * HIDD];
__device__ __nv_bfloat16 g_Wal[(size_t)HIDD * HIDD];
__device__ __nv_bfloat16 g_Wbh[(size_t)HIDD * HIDD];
__device__ __nv_bfloat16 g_Wbl[(size_t)HIDD * HIDD];
__device__ __nv_bfloat16 g_W2h[(size_t)OUTD * HIDD];
__device__ __nv_bfloat16 g_W2l[(size_t)OUTD * HIDD];

// ===========================================================================
// Helpers (base compute_103 features only: mma.sync / ldmatrix / cp.async)
// ===========================================================================
__device__ __forceinline__ uint32_t smem_to_u32(const void* p) {
    uint32_t a;
    asm("{ .reg .u64 t; cvta.to.shared.u64 t, %1; cvt.u32.u64 %0, t; }"
        : "=r"(a) : "l"(p));
    return a;
}

__device__ __forceinline__ void cp_async16(uint32_t saddr, const void* gaddr) {
    asm volatile("cp.async.cg.shared.global [%0], [%1], 16;"
                 :: "r"(saddr), "l"(gaddr) : "memory");
}
__device__ __forceinline__ void cp_commit() {
    asm volatile("cp.async.commit_group;" ::: "memory");
}
template <int N>
__device__ __forceinline__ void cp_wait() {
    asm volatile("cp.async.wait_group %0;" :: "n"(N) : "memory");
}

__device__ __forceinline__ void ldsm4(uint32_t* r, uint32_t addr) {
    asm volatile("ldmatrix.sync.aligned.m8n8.x4.shared.b16 {%0,%1,%2,%3}, [%4];"
                 : "=r"(r[0]), "=r"(r[1]), "=r"(r[2]), "=r"(r[3]) : "r"(addr));
}

__device__ __forceinline__ void mma16816(float* c, const uint32_t* a,
                                         uint32_t b0, uint32_t b1) {
    asm volatile(
        "mma.sync.aligned.m16n8k16.row.col.f32.bf16.bf16.f32 "
        "{%0,%1,%2,%3}, {%4,%5,%6,%7}, {%8,%9}, {%0,%1,%2,%3};"
        : "+f"(c[0]), "+f"(c[1]), "+f"(c[2]), "+f"(c[3])
        : "r"(a[0]), "r"(a[1]), "r"(a[2]), "r"(a[3]), "r"(b0), "r"(b1));
}

__device__ __forceinline__ void split_bf16(float v, __nv_bfloat16& h, __nv_bfloat16& l) {
    h = __float2bfloat16_rn(v);
    l = __float2bfloat16_rn(v - __bfloat162float(h));
}

// ===========================================================================
// Misc small kernels
// ===========================================================================
__global__ void zero_accum_kernel() { g_loss = 0.0; g_correct = 0; }

// Transpose W[K,N] -> (hi,lo) bf16 [N,K]
__global__ void tsplit_kernel(const float* __restrict__ W,
                              __nv_bfloat16* __restrict__ TH,
                              __nv_bfloat16* __restrict__ TL,
                              int K, int N)
{
    __shared__ float t[32][33];
    int k0 = blockIdx.x * 32, n0 = blockIdx.y * 32;
    int tx = threadIdx.x, ty = threadIdx.y;   // 32 x 8
#pragma unroll
    for (int i = 0; i < 32; i += 8)
        t[ty + i][tx] = W[(size_t)(k0 + ty + i) * N + n0 + tx];
    __syncthreads();
#pragma unroll
    for (int i = 0; i < 32; i += 8) {
        float v = t[tx][ty + i];
        __nv_bfloat16 h, l;
        split_bf16(v, h, l);
        size_t o = (size_t)(n0 + ty + i) * K + k0 + tx;
        TH[o] = h;
        TL[o] = l;
    }
}

// LN1 + split
__global__ void ln1_split_kernel(const float* __restrict__ x,
                                 const float* __restrict__ g,
                                 const float* __restrict__ b)
{
    int row = blockIdx.x, tid = threadIdx.x;
    const float* xr = x + (size_t)row * INPD;
    float v[12];
    float s = 0.f, ss = 0.f;
#pragma unroll
    for (int i = 0; i < 12; i++) {
        int j = tid + i * 256;
        v[i] = xr[j];
        s += v[i]; ss += v[i] * v[i];
    }
    __shared__ float sh[256], sh2[256];
    sh[tid] = s; sh2[tid] = ss;
    __syncthreads();
    for (int o = 128; o > 0; o >>= 1) {
        if (tid < o) { sh[tid] += sh[tid + o]; sh2[tid] += sh2[tid + o]; }
        __syncthreads();
    }
    __shared__ float sm, sr;
    if (tid == 0) {
        float m = sh[0] / (float)INPD;
        float var = sh2[0] / (float)INPD - m * m;
        sm = m; sr = rsqrtf(var + LN_EPS);
    }
    __syncthreads();
    float m = sm, r = sr;
#pragma unroll
    for (int i = 0; i < 12; i++) {
        int j = tid + i * 256;
        float t = (v[i] - m) * r * g[j] + b[j];
        __nv_bfloat16 h, l;
        split_bf16(t, h, l);
        size_t o = (size_t)row * INPD + j;
        g_A1h[o] = h; g_A1l[o] = l;
    }
}

// ===========================================================================
// Tensor-core GEMM via mma.sync: C[M,N] = ep(A @ B^T)
// A=[M,K] bf16 pair, B=[N,K] bf16 pair; bf16x3: hh + hl + lh, fp32 accum.
// Block tile 256x128, 8 warps (4m x 2n), warp tile 64x64, k-chunk 32,
// 3-stage cp.async pipeline, ONE __syncthreads per chunk.
// Smem rows padded to 80B -> conflict-free LDSM.
// Requires M%256==0, N%128==0, K%32==0, K/32 >= 3.
// ===========================================================================
#define SMS    80                       // smem row stride in bytes
#define A_BUF  (256 * SMS)              // 20480
#define B_BUF  (128 * SMS)              // 10240
#define OFF_AH 0
#define OFF_AL A_BUF
#define OFF_BH (2 * A_BUF)
#define OFF_BL (2 * A_BUF + B_BUF)
#define STAGE  (2 * A_BUF + 2 * B_BUF)  // 61440
#define NSTAGE 3
#define GEMM_SMEM_BYTES (NSTAGE * STAGE)

__global__ void __launch_bounds__(256, 1)
tc_gemm(const __nv_bfloat16* __restrict__ AHi, const __nv_bfloat16* __restrict__ ALo,
        const __nv_bfloat16* __restrict__ BHi, const __nv_bfloat16* __restrict__ BLo,
        const float* __restrict__ bias, const float* __restrict__ resid,
        float* __restrict__ C,
        __nv_bfloat16* __restrict__ CHi, __nv_bfloat16* __restrict__ CLo,
        int N, int K, int doRelu)
{
    extern __shared__ char smem[];
    const uint32_t sbase = smem_to_u32(smem);
    const int tid = threadIdx.x;
    const int wid = tid >> 5, lid = tid & 31;
    const int wm = wid & 3, wn = wid >> 2;     // 4m x 2n warp grid
    const int m0 = blockIdx.y * 256, n0 = blockIdx.x * 128;
    const size_t ldb = (size_t)K * 2;          // bytes per row

    const char* gAh = (const char*)AHi + (size_t)m0 * ldb;
    const char* gAl = (const char*)ALo + (size_t)m0 * ldb;
    const char* gBh = (const char*)BHi + (size_t)n0 * ldb;
    const char* gBl = (const char*)BLo + (size_t)n0 * ldb;

    // ldmatrix lane offsets
    const uint32_t aOff = (uint32_t)((wm * 64 + (lid & 15)) * SMS) + ((lid >> 4) << 4);
    const uint32_t bOff = (uint32_t)((wn * 64 + (lid & 7) + ((lid >> 4) << 3)) * SMS)
                        + (((lid >> 3) & 1) << 4);

    float acc[4][8][4];
#pragma unroll
    for (int i = 0; i < 4; i++)
#pragma unroll
        for (int j = 0; j < 8; j++)
#pragma unroll
            for (int q = 0; q < 4; q++) acc[i][j][q] = 0.f;

    const int nch = K >> 5;                     // k-chunks of 32

    auto issue = [&](int kt) {
        const uint32_t st = sbase + (uint32_t)(kt % NSTAGE) * STAGE;
        const size_t kb = (size_t)kt * 64;      // 32 bf16 = 64 bytes
        // A: 256 rows x 4 chunks = 1024 chunks; 4 iters of 256 threads
#pragma unroll
        for (int it = 0; it < 4; it++) {
            int idx = it * 256 + tid;
            int row = idx >> 2;
            uint32_t chb = (uint32_t)(idx & 3) << 4;
            uint32_t so = (uint32_t)row * SMS + chb;
            size_t go = (size_t)row * ldb + kb + chb;
            cp_async16(st + OFF_AH + so, gAh + go);
            cp_async16(st + OFF_AL + so, gAl + go);
        }
        // B: 128 rows x 4 chunks = 512 chunks; 2 iters
#pragma unroll
        for (int it = 0; it < 2; it++) {
            int idx = it * 256 + tid;
            int row = idx >> 2;
            uint32_t chb = (uint32_t)(idx & 3) << 4;
            uint32_t so = (uint32_t)row * SMS + chb;
            size_t go = (size_t)row * ldb + kb + chb;
            cp_async16(st + OFF_BH + so, gBh + go);
            cp_async16(st + OFF_BL + so, gBl + go);
        }
        cp_commit();
    };

    issue(0);
    issue(1);
    for (int kt = 0; kt < nch; kt++) {
        if (kt == nch - 1) cp_wait<0>();
        else               cp_wait<1>();
        __syncthreads();

        const uint32_t st = sbase + (uint32_t)(kt % NSTAGE) * STAGE;
#pragma unroll
        for (int kk = 0; kk < 2; kk++) {
            const uint32_t kkB = kk << 5;       // 16 bf16 = 32 bytes
            uint32_t bh[4][4], bl[4][4];
#pragma unroll
            for (int np = 0; np < 4; np++) {
                ldsm4(bh[np], st + OFF_BH + bOff + (uint32_t)np * 16 * SMS + kkB);
                ldsm4(bl[np], st + OFF_BL + bOff + (uint32_t)np * 16 * SMS + kkB);
            }
#pragma unroll
            for (int mi = 0; mi < 4; mi++) {
                uint32_t ah[4], al[4];
                ldsm4(ah, st + OFF_AH + aOff + (uint32_t)mi * 16 * SMS + kkB);
                ldsm4(al, st + OFF_AL + aOff + (uint32_t)mi * 16 * SMS + kkB);
#pragma unroll
                for (int ni = 0; ni < 8; ni++) {
                    const int np = ni >> 1, hh = (ni & 1) << 1;
                    mma16816(acc[mi][ni], ah, bh[np][hh], bh[np][hh + 1]);
                    mma16816(acc[mi][ni], ah, bl[np][hh], bl[np][hh + 1]);
                    mma16816(acc[mi][ni], al, bh[np][hh], bh[np][hh + 1]);
                }
            }
        }
        if (kt + 2 < nch) issue(kt + 2);
    }

    // ---- epilogue ----
#pragma unroll
    for (int mi = 0; mi < 4; mi++) {
#pragma unroll
        for (int ni = 0; ni < 8; ni++) {
            const int col = n0 + wn * 64 + ni * 8 + ((lid & 3) << 1);
#pragma unroll
            for (int half = 0; half < 2; half++) {
                const int row = m0 + wm * 64 + mi * 16 + (lid >> 2) + half * 8;
                float v0 = acc[mi][ni][half * 2 + 0];
                float v1 = acc[mi][ni][half * 2 + 1];
                if (bias) { v0 += bias[col]; v1 += bias[col + 1]; }
                if (doRelu) { v0 = fmaxf(v0, 0.f); v1 = fmaxf(v1, 0.f); }
                if (resid) {
                    float2 r = *(const float2*)(resid + (size_t)row * N + col);
                    v0 += r.x; v1 += r.y;
                }
                if (C) {
                    float2 w; w.x = v0; w.y = v1;
                    *(float2*)(C + (size_t)row * N + col) = w;
                }
                if (CHi) {
                    __nv_bfloat16 h0, l0, h1, l1;
                    split_bf16(v0, h0, l0);
                    split_bf16(v1, h1, l1);
                    uint32_t ph = (uint32_t)__bfloat16_as_ushort(h0) |
                                  ((uint32_t)__bfloat16_as_ushort(h1) << 16);
                    uint32_t pl = (uint32_t)__bfloat16_as_ushort(l0) |
                                  ((uint32_t)__bfloat16_as_ushort(l1) << 16);
                    *(uint32_t*)(CHi + (size_t)row * N + col) = ph;
                    *(uint32_t*)(CLo + (size_t)row * N + col) = pl;
                }
            }
        }
    }
}

// ===========================================================================
// LN2 + normalize + split; write pred (f32) and PN pair.
// ===========================================================================
__global__ void ln2_norm_kernel(const float* __restrict__ P,
                                const float* __restrict__ g,
                                const float* __restrict__ b,
                                float* __restrict__ pred)
{
    int row = blockIdx.x, tid = threadIdx.x;
    const float* pr = P + (size_t)row * OUTD;
    float v[3];
    float s = 0.f, ss = 0.f;
#pragma unroll
    for (int i = 0; i < 3; i++) {
        int j = tid + i * 256;
        v[i] = pr[j];
        s += v[i]; ss += v[i] * v[i];
    }
    __shared__ float sh[256], sh2[256];
    sh[tid] = s; sh2[tid] = ss;
    __syncthreads();
    for (int o = 128; o > 0; o >>= 1) {
        if (tid < o) { sh[tid] += sh[tid + o]; sh2[tid] += sh2[tid + o]; }
        __syncthreads();
    }
    __shared__ float smean, srstd;
    if (tid == 0) {
        float m = sh[0] / (float)OUTD;
        float var = sh2[0] / (float)OUTD - m * m;
        smean = m; srstd = rsqrtf(var + LN_EPS);
    }
    __syncthreads();
    float t[3];
    float tss = 0.f;
#pragma unroll
    for (int i = 0; i < 3; i++) {
        int j = tid + i * 256;
        t[i] = (v[i] - smean) * srstd * g[j] + b[j];
        tss += t[i] * t[i];
    }
    __syncthreads();
    sh[tid] = tss;
    __syncthreads();
    for (int o = 128; o > 0; o >>= 1) {
        if (tid < o) sh[tid] += sh[tid + o];
        __syncthreads();
    }
    __shared__ float sinv;
    if (tid == 0) sinv = 1.f / sqrtf(sh[0]);
    __syncthreads();
    float* pw = pred + (size_t)row * OUTD;
#pragma unroll
    for (int i = 0; i < 3; i++) {
        int j = tid + i * 256;
        pw[j] = t[i];
        float pn = t[i] * sinv;
        __nv_bfloat16 h, l;
        split_bf16(pn, h, l);
        size_t o = (size_t)row * OUTD + j;
        g_PNh[o] = h; g_PNl[o] = l;
    }
}

__global__ void ynorm_kernel(const float* __restrict__ y)
{
    int row = blockIdx.x, tid = threadIdx.x;
    const float* yr = y + (size_t)row * OUTD;
    float v[3];
    float ss = 0.f;
#pragma unroll
    for (int i = 0; i < 3; i++) {
        int j = tid + i * 256;
        v[i] = yr[j];
        ss += v[i] * v[i];
    }
    __shared__ float sh[256];
    sh[tid] = ss;
    __syncthreads();
    for (int o = 128; o > 0; o >>= 1) {
        if (tid < o) sh[tid] += sh[tid + o];
        __syncthreads();
    }
    __shared__ float sinv;
    if (tid == 0) sinv = 1.f / sqrtf(sh[0]);
    __syncthreads();
#pragma unroll
    for (int i = 0; i < 3; i++) {
        int j = tid + i * 256;
        float yn = v[i] * sinv;
        __nv_bfloat16 h, l;
        split_bf16(yn, h, l);
        size_t o = (size_t)row * OUTD + j;
        g_YNh[o] = h; g_YNl[o] = l;
    }
}

// ===========================================================================
// Reduce S: per-row argmax (first occurrence) + logsumexp.
// ===========================================================================
__global__ void reduce_S_kernel()
{
    int row = blockIdx.x, tid = threadIdx.x;
    const float* sr = g_S + (size_t)row * BSZ;

    float best = -3.4e38f;
    int bidx = 0x7fffffff;
    for (int j = tid; j < BSZ; j += 256) {
        float v = sr[j];
        if (v > best || (v == best && j < bidx)) { best = v; bidx = j; }
    }
    __shared__ float shv[256];
    __shared__ int   shi[256];
    shv[tid] = best; shi[tid] = bidx;
    __syncthreads();
    for (int o = 128; o > 0; o >>= 1) {
        if (tid < o) {
            float vo = shv[tid + o]; int io = shi[tid + o];
            if (vo > shv[tid] || (vo == shv[tid] && io < shi[tid])) {
                shv[tid] = vo; shi[tid] = io;
            }
        }
        __syncthreads();
    }
    __shared__ float smax;
    __shared__ int   samax;
    if (tid == 0) { smax = shv[0]; samax = shi[0]; }
    __syncthreads();

    float se = 0.f;
    for (int j = tid; j < BSZ; j += 256) se += __expf(sr[j] - smax);
    shv[tid] = se;
    __syncthreads();
    for (int o = 128; o > 0; o >>= 1) {
        if (tid < o) shv[tid] += shv[tid + o];
        __syncthreads();
    }
    if (tid == 0) {
        float lse = smax + __logf(shv[0]);
        double contrib = (double)lse - (double)sr[row];
        atomicAdd(&g_loss, contrib);
        if (samax == row) atomicAdd(&g_correct, 1);
    }
}

__global__ void finalize_kernel(float* __restrict__ out, int out_size)
{
    const int NP = BSZ * OUTD;
    if (out_size >= NP + 2) {
        out[NP]     = (float)g_loss;
        out[NP + 1] = (float)g_correct / (float)BSZ;
    }
}

// ===========================================================================
extern "C" void kernel_launch(void* const* d_in, const int* in_sizes, int n_in,
                              void* d_out, int out_size)
{
    const float* inp  = (const float*)d_in[0];
    const float* y    = (const float*)d_in[1];
    const float* ln1g = (const float*)d_in[2];
    const float* ln1b = (const float*)d_in[3];
    const float* W1   = (const float*)d_in[4];
    const float* b1   = (const float*)d_in[5];
    const float* Wa   = (const float*)d_in[6];
    const float* ba   = (const float*)d_in[7];
    const float* Wb   = (const float*)d_in[8];
    const float* bb   = (const float*)d_in[9];
    const float* W2   = (const float*)d_in[10];
    const float* b2   = (const float*)d_in[11];
    const float* ln2g = (const float*)d_in[12];
    const float* ln2b = (const float*)d_in[13];
    float* out = (float*)d_out;

    static int smem_cfg_done = 0;
    if (!smem_cfg_done) {
        cudaFuncSetAttribute(tc_gemm, cudaFuncAttributeMaxDynamicSharedMemorySize,
                             GEMM_SMEM_BYTES);
        smem_cfg_done = 1;
    }

    float *H, *P, *S;
    cudaGetSymbolAddress((void**)&H, g_H);
    cudaGetSymbolAddress((void**)&P, g_P);
    cudaGetSymbolAddress((void**)&S, g_S);
    __nv_bfloat16 *A1h, *A1l, *Hh, *Hl, *Th, *Tl, *PNh, *PNl, *YNh, *YNl;
    __nv_bfloat16 *W1h, *W1l, *Wah, *Wal, *Wbh, *Wbl, *W2h, *W2l;
    cudaGetSymbolAddress((void**)&A1h, g_A1h);
    cudaGetSymbolAddress((void**)&A1l, g_A1l);
    cudaGetSymbolAddress((void**)&Hh,  g_Hh);
    cudaGetSymbolAddress((void**)&Hl,  g_Hl);
    cudaGetSymbolAddress((void**)&Th,  g_Th);
    cudaGetSymbolAddress((void**)&Tl,  g_Tl);
    cudaGetSymbolAddress((void**)&PNh, g_PNh);
    cudaGetSymbolAddress((void**)&PNl, g_PNl);
    cudaGetSymbolAddress((void**)&YNh, g_YNh);
    cudaGetSymbolAddress((void**)&YNl, g_YNl);
    cudaGetSymbolAddress((void**)&W1h, g_W1h);
    cudaGetSymbolAddress((void**)&W1l, g_W1l);
    cudaGetSymbolAddress((void**)&Wah, g_Wah);
    cudaGetSymbolAddress((void**)&Wal, g_Wal);
    cudaGetSymbolAddress((void**)&Wbh, g_Wbh);
    cudaGetSymbolAddress((void**)&Wbl, g_Wbl);
    cudaGetSymbolAddress((void**)&W2h, g_W2h);
    cudaGetSymbolAddress((void**)&W2l, g_W2l);

    zero_accum_kernel<<<1, 1>>>();

    // Weight transpose + bf16 split
    dim3 tb(32, 8);
    tsplit_kernel<<<dim3(INPD / 32, HIDD / 32), tb>>>(W1, W1h, W1l, INPD, HIDD);
    tsplit_kernel<<<dim3(HIDD / 32, HIDD / 32), tb>>>(Wa, Wah, Wal, HIDD, HIDD);
    tsplit_kernel<<<dim3(HIDD / 32, HIDD / 32), tb>>>(Wb, Wbh, Wbl, HIDD, HIDD);
    tsplit_kernel<<<dim3(HIDD / 32, OUTD / 32), tb>>>(W2, W2h, W2l, HIDD, OUTD);

    // LN1 + split input
    ln1_split_kernel<<<BSZ, 256>>>(inp, ln1g, ln1b);

    // H = LN1(inp) @ W1 + b1   [8192,1024] K=3072 -> f32 H + pair
    tc_gemm<<<dim3(HIDD / 128, BSZ / 256), 256, GEMM_SMEM_BYTES>>>(
        A1h, A1l, W1h, W1l, b1, nullptr, H, Hh, Hl, HIDD, INPD, 0);

    // Residual blocks (shared weights), x2
    for (int r = 0; r < 2; r++) {
        tc_gemm<<<dim3(HIDD / 128, BSZ / 256), 256, GEMM_SMEM_BYTES>>>(
            Hh, Hl, Wah, Wal, ba, nullptr, nullptr, Th, Tl, HIDD, HIDD, 1);
        tc_gemm<<<dim3(HIDD / 128, BSZ / 256), 256, GEMM_SMEM_BYTES>>>(
            Th, Tl, Wbh, Wbl, bb, H, H, Hh, Hl, HIDD, HIDD, 1);
    }

    // P = H @ W2 + b2   [8192,768] K=1024 -> f32 only
    tc_gemm<<<dim3(OUTD / 128, BSZ / 256), 256, GEMM_SMEM_BYTES>>>(
        Hh, Hl, W2h, W2l, b2, nullptr, P, nullptr, nullptr, OUTD, HIDD, 0);

    // pred = LN2(P); PN pair; YN pair
    ln2_norm_kernel<<<BSZ, 256>>>(P, ln2g, ln2b, out);
    ynorm_kernel<<<BSZ, 256>>>(y);

    // S = PN @ YN^T   [8192,8192] K=768 -> f32
    tc_gemm<<<dim3(BSZ / 128, BSZ / 256), 256, GEMM_SMEM_BYTES>>>(
        PNh, PNl, YNh, YNl, nullptr, nullptr, S, nullptr, nullptr, BSZ, OUTD, 0);

    reduce_S_kernel<<<BSZ, 256>>>();
    finalize_kernel<<<1, 1>>>(out, out_size);
}

// round 6
// speedup vs baseline: 3.5745x; 1.5222x over previous
#include <cuda_runtime.h>
#include <cuda_bf16.h>
#include <math.h>
#include <stdint.h>

#define BSZ  8192
#define INPD 3072
#define HIDD 1024
#define OUTD 768
#define LN_EPS 1e-5f

// ===========================================================================
// Scratch (__device__ globals; no allocations allowed anywhere).
// ===========================================================================
__device__ float g_H[(size_t)BSZ * HIDD];
__device__ float g_P[(size_t)BSZ * OUTD];
__device__ float g_S[(size_t)BSZ * BSZ];
__device__ double g_loss;
__device__ int    g_correct;

// bf16 hi/lo split operand buffers
__device__ __nv_bfloat16 g_A1h[(size_t)BSZ * INPD];
__device__ __nv_bfloat16 g_A1l[(size_t)BSZ * INPD];
__device__ __nv_bfloat16 g_Hh[(size_t)BSZ * HIDD];
__device__ __nv_bfloat16 g_Hl[(size_t)BSZ * HIDD];
__device__ __nv_bfloat16 g_Th[(size_t)BSZ * HIDD];
__device__ __nv_bfloat16 g_Tl[(size_t)BSZ * HIDD];
__device__ __nv_bfloat16 g_PNh[(size_t)BSZ * OUTD];
__device__ __nv_bfloat16 g_PNl[(size_t)BSZ * OUTD];
__device__ __nv_bfloat16 g_YNh[(size_t)BSZ * OUTD];
__device__ __nv_bfloat16 g_YNl[(size_t)BSZ * OUTD];
// transposed + split weights: layout [N rows][K cols], K-major
__device__ __nv_bfloat16 g_W1h[(size_t)HIDD * INPD];
__device__ __nv_bfloat16 g_W1l[(size_t)HIDD * INPD];
__device__ __nv_bfloat16 g_Wah[(size_t)HIDD * HIDD];
__device__ __nv_bfloat16 g_Wal[(size_t)HIDD * HIDD];
__device__ __nv_bfloat16 g_Wbh[(size_t)HIDD * HIDD];
__device__ __nv_bfloat16 g_Wbl[(size_t)HIDD * HIDD];
__device__ __nv_bfloat16 g_W2h[(size_t)OUTD * HIDD];
__device__ __nv_bfloat16 g_W2l[(size_t)OUTD * HIDD];

// ===========================================================================
// Helpers (base compute_103 features only: mma.sync / ldmatrix / cp.async)
// ===========================================================================
__device__ __forceinline__ uint32_t smem_to_u32(const void* p) {
    uint32_t a;
    asm("{ .reg .u64 t; cvta.to.shared.u64 t, %1; cvt.u32.u64 %0, t; }"
        : "=r"(a) : "l"(p));
    return a;
}

__device__ __forceinline__ void cp_async16(uint32_t saddr, const void* gaddr) {
    asm volatile("cp.async.cg.shared.global [%0], [%1], 16;"
                 :: "r"(saddr), "l"(gaddr) : "memory");
}
__device__ __forceinline__ void cp_commit() {
    asm volatile("cp.async.commit_group;" ::: "memory");
}
template <int N>
__device__ __forceinline__ void cp_wait() {
    asm volatile("cp.async.wait_group %0;" :: "n"(N) : "memory");
}

__device__ __forceinline__ void ldsm4(uint32_t* r, uint32_t addr) {
    asm volatile("ldmatrix.sync.aligned.m8n8.x4.shared.b16 {%0,%1,%2,%3}, [%4];"
                 : "=r"(r[0]), "=r"(r[1]), "=r"(r[2]), "=r"(r[3]) : "r"(addr));
}

__device__ __forceinline__ void mma16816(float* c, const uint32_t* a,
                                         uint32_t b0, uint32_t b1) {
    asm volatile(
        "mma.sync.aligned.m16n8k16.row.col.f32.bf16.bf16.f32 "
        "{%0,%1,%2,%3}, {%4,%5,%6,%7}, {%8,%9}, {%0,%1,%2,%3};"
        : "+f"(c[0]), "+f"(c[1]), "+f"(c[2]), "+f"(c[3])
        : "r"(a[0]), "r"(a[1]), "r"(a[2]), "r"(a[3]), "r"(b0), "r"(b1));
}

__device__ __forceinline__ void split_bf16(float v, __nv_bfloat16& h, __nv_bfloat16& l) {
    h = __float2bfloat16_rn(v);
    l = __float2bfloat16_rn(v - __bfloat162float(h));
}

// ===========================================================================
// tsplit_all: transpose+split all four weights in ONE launch.
// blockIdx.z selects the weight; over-provisioned grid with guards.
// ===========================================================================
__global__ void tsplit_all_kernel(const float* __restrict__ W1,
                                  const float* __restrict__ Wa,
                                  const float* __restrict__ Wb,
                                  const float* __restrict__ W2)
{
    const float* W; __nv_bfloat16 *TH, *TL; int K, N;
    switch (blockIdx.z) {
        case 0: W = W1; TH = g_W1h; TL = g_W1l; K = INPD; N = HIDD; break;
        case 1: W = Wa; TH = g_Wah; TL = g_Wal; K = HIDD; N = HIDD; break;
        case 2: W = Wb; TH = g_Wbh; TL = g_Wbl; K = HIDD; N = HIDD; break;
        default: W = W2; TH = g_W2h; TL = g_W2l; K = HIDD; N = OUTD; break;
    }
    int k0 = blockIdx.x * 32, n0 = blockIdx.y * 32;
    if (k0 >= K || n0 >= N) return;

    __shared__ float t[32][33];
    int tx = threadIdx.x, ty = threadIdx.y;   // 32 x 8
#pragma unroll
    for (int i = 0; i < 32; i += 8)
        t[ty + i][tx] = W[(size_t)(k0 + ty + i) * N + n0 + tx];
    __syncthreads();
#pragma unroll
    for (int i = 0; i < 32; i += 8) {
        float v = t[tx][ty + i];
        __nv_bfloat16 h, l;
        split_bf16(v, h, l);
        size_t o = (size_t)(n0 + ty + i) * K + k0 + tx;
        TH[o] = h;
        TL[o] = l;
    }
}

// LN1 + split (also zeroes the loss accumulators from block 0).
__global__ void ln1_split_kernel(const float* __restrict__ x,
                                 const float* __restrict__ g,
                                 const float* __restrict__ b)
{
    int row = blockIdx.x, tid = threadIdx.x;
    if (row == 0 && tid == 0) { g_loss = 0.0; g_correct = 0; }
    const float* xr = x + (size_t)row * INPD;
    float v[12];
    float s = 0.f, ss = 0.f;
#pragma unroll
    for (int i = 0; i < 12; i++) {
        int j = tid + i * 256;
        v[i] = xr[j];
        s += v[i]; ss += v[i] * v[i];
    }
    __shared__ float sh[256], sh2[256];
    sh[tid] = s; sh2[tid] = ss;
    __syncthreads();
    for (int o = 128; o > 0; o >>= 1) {
        if (tid < o) { sh[tid] += sh[tid + o]; sh2[tid] += sh2[tid + o]; }
        __syncthreads();
    }
    __shared__ float sm, sr;
    if (tid == 0) {
        float m = sh[0] / (float)INPD;
        float var = sh2[0] / (float)INPD - m * m;
        sm = m; sr = rsqrtf(var + LN_EPS);
    }
    __syncthreads();
    float m = sm, r = sr;
#pragma unroll
    for (int i = 0; i < 12; i++) {
        int j = tid + i * 256;
        float t = (v[i] - m) * r * g[j] + b[j];
        __nv_bfloat16 h, l;
        split_bf16(t, h, l);
        size_t o = (size_t)row * INPD + j;
        g_A1h[o] = h; g_A1l[o] = l;
    }
}

// ===========================================================================
// Persistent tensor-core GEMM via mma.sync: C[M,N] = ep(A @ B^T)
// A=[M,K] bf16 pair, B=[N,K] bf16 pair; bf16x3: hh + hl + lh, fp32 accum.
// Block tile 256x128, 8 warps (4m x 2n), warp tile 64x64, k-chunk 64,
// 2-stage cp.async ring; persistent over output tiles (grid ~= #SMs).
// Smem rows padded to 144B -> conflict-free LDSM.
// Requires M%256==0, N%128==0, K%64==0.
// ===========================================================================
#define SMS    144                      // smem row stride in bytes (128 + 16 pad)
#define A_BUF  (256 * SMS)              // 36864
#define B_BUF  (128 * SMS)              // 18432
#define OFF_AH 0
#define OFF_AL A_BUF
#define OFF_BH (2 * A_BUF)
#define OFF_BL (2 * A_BUF + B_BUF)
#define STAGE  (2 * A_BUF + 2 * B_BUF)  // 110592
#define GEMM_SMEM_BYTES (2 * STAGE)     // 221184

__global__ void __launch_bounds__(256, 1)
tc_gemm(const __nv_bfloat16* __restrict__ AHi, const __nv_bfloat16* __restrict__ ALo,
        const __nv_bfloat16* __restrict__ BHi, const __nv_bfloat16* __restrict__ BLo,
        const float* __restrict__ bias, const float* __restrict__ resid,
        float* __restrict__ C,
        __nv_bfloat16* __restrict__ CHi, __nv_bfloat16* __restrict__ CLo,
        int M, int N, int K, int doRelu)
{
    extern __shared__ char smem[];
    const uint32_t sbase = smem_to_u32(smem);
    const int tid = threadIdx.x;
    const int wid = tid >> 5, lid = tid & 31;
    const int wm = wid & 3, wn = wid >> 2;     // 4m x 2n warp grid
    const size_t ldb = (size_t)K * 2;          // bytes per row
    const int nch = K >> 6;                    // k-chunks of 64
    const int ntN = N >> 7, ntM = M >> 8;
    const int ntotal = ntN * ntM;

    // ldmatrix lane offsets
    const uint32_t aOff = (uint32_t)((wm * 64 + (lid & 15)) * SMS) + ((lid >> 4) << 4);
    const uint32_t bOff = (uint32_t)((wn * 64 + (lid & 7) + ((lid >> 4) << 3)) * SMS)
                        + (((lid >> 3) & 1) << 4);

    // loader mapping: idx -> row (idx>>3), 16B chunk (idx&7)
    for (int t = blockIdx.x; t < ntotal; t += gridDim.x) {
        const int bx = t % ntN, by = t / ntN;
        const int m0 = by * 256, n0 = bx * 128;
        const char* gAh = (const char*)AHi + (size_t)m0 * ldb;
        const char* gAl = (const char*)ALo + (size_t)m0 * ldb;
        const char* gBh = (const char*)BHi + (size_t)n0 * ldb;
        const char* gBl = (const char*)BLo + (size_t)n0 * ldb;

        float acc[4][8][4];
#pragma unroll
        for (int i = 0; i < 4; i++)
#pragma unroll
            for (int j = 0; j < 8; j++)
#pragma unroll
                for (int q = 0; q < 4; q++) acc[i][j][q] = 0.f;

        auto issue = [&](int kt) {
            const uint32_t st = sbase + (uint32_t)(kt & 1) * STAGE;
            const size_t kb = (size_t)kt << 7;     // 64 bf16 = 128 bytes
            // A: 256 rows x 8 chunks = 2048; 8 iters of 256 threads
#pragma unroll
            for (int it = 0; it < 8; it++) {
                int idx = it * 256 + tid;
                int row = idx >> 3;
                uint32_t chb = (uint32_t)(idx & 7) << 4;
                uint32_t so = (uint32_t)row * SMS + chb;
                size_t go = (size_t)row * ldb + kb + chb;
                cp_async16(st + OFF_AH + so, gAh + go);
                cp_async16(st + OFF_AL + so, gAl + go);
            }
            // B: 128 rows x 8 chunks = 1024; 4 iters
#pragma unroll
            for (int it = 0; it < 4; it++) {
                int idx = it * 256 + tid;
                int row = idx >> 3;
                uint32_t chb = (uint32_t)(idx & 7) << 4;
                uint32_t so = (uint32_t)row * SMS + chb;
                size_t go = (size_t)row * ldb + kb + chb;
                cp_async16(st + OFF_BH + so, gBh + go);
                cp_async16(st + OFF_BL + so, gBl + go);
            }
            cp_commit();
        };

        issue(0);
        cp_wait<0>();
        __syncthreads();

        for (int kt = 0; kt < nch; kt++) {
            if (kt + 1 < nch) issue(kt + 1);

            const uint32_t st = sbase + (uint32_t)(kt & 1) * STAGE;
#pragma unroll
            for (int kk = 0; kk < 4; kk++) {
                const uint32_t kkB = (uint32_t)kk << 5;   // 16 bf16 = 32 bytes
                uint32_t bh[4][4], bl[4][4];
#pragma unroll
                for (int np = 0; np < 4; np++) {
                    ldsm4(bh[np], st + OFF_BH + bOff + (uint32_t)np * 16 * SMS + kkB);
                    ldsm4(bl[np], st + OFF_BL + bOff + (uint32_t)np * 16 * SMS + kkB);
                }
#pragma unroll
                for (int mi = 0; mi < 4; mi++) {
                    uint32_t ah[4], al[4];
                    ldsm4(ah, st + OFF_AH + aOff + (uint32_t)mi * 16 * SMS + kkB);
                    ldsm4(al, st + OFF_AL + aOff + (uint32_t)mi * 16 * SMS + kkB);
#pragma unroll
                    for (int ni = 0; ni < 8; ni++) {
                        const int np = ni >> 1, hh = (ni & 1) << 1;
                        mma16816(acc[mi][ni], ah, bh[np][hh], bh[np][hh + 1]);
                        mma16816(acc[mi][ni], ah, bl[np][hh], bl[np][hh + 1]);
                        mma16816(acc[mi][ni], al, bh[np][hh], bh[np][hh + 1]);
                    }
                }
            }

            if (kt + 1 < nch) {
                cp_wait<0>();
                __syncthreads();
            }
        }

        // ---- epilogue ----
#pragma unroll
        for (int mi = 0; mi < 4; mi++) {
#pragma unroll
            for (int ni = 0; ni < 8; ni++) {
                const int col = n0 + wn * 64 + ni * 8 + ((lid & 3) << 1);
#pragma unroll
                for (int half = 0; half < 2; half++) {
                    const int row = m0 + wm * 64 + mi * 16 + (lid >> 2) + half * 8;
                    float v0 = acc[mi][ni][half * 2 + 0];
                    float v1 = acc[mi][ni][half * 2 + 1];
                    if (bias) { v0 += bias[col]; v1 += bias[col + 1]; }
                    if (doRelu) { v0 = fmaxf(v0, 0.f); v1 = fmaxf(v1, 0.f); }
                    if (resid) {
                        float2 r = *(const float2*)(resid + (size_t)row * N + col);
                        v0 += r.x; v1 += r.y;
                    }
                    if (C) {
                        float2 w; w.x = v0; w.y = v1;
                        *(float2*)(C + (size_t)row * N + col) = w;
                    }
                    if (CHi) {
                        __nv_bfloat16 h0, l0, h1, l1;
                        split_bf16(v0, h0, l0);
                        split_bf16(v1, h1, l1);
                        uint32_t ph = (uint32_t)__bfloat16_as_ushort(h0) |
                                      ((uint32_t)__bfloat16_as_ushort(h1) << 16);
                        uint32_t pl = (uint32_t)__bfloat16_as_ushort(l0) |
                                      ((uint32_t)__bfloat16_as_ushort(l1) << 16);
                        *(uint32_t*)(CHi + (size_t)row * N + col) = ph;
                        *(uint32_t*)(CLo + (size_t)row * N + col) = pl;
                    }
                }
            }
        }
        __syncthreads();   // protect smem stages before next tile's issue(0)
    }
}

// ===========================================================================
// LN2 + normalize + split; write pred (f32) and PN pair.
// ===========================================================================
__global__ void ln2_norm_kernel(const float* __restrict__ P,
                                const float* __restrict__ g,
                                const float* __restrict__ b,
                                float* __restrict__ pred)
{
    int row = blockIdx.x, tid = threadIdx.x;
    const float* pr = P + (size_t)row * OUTD;
    float v[3];
    float s = 0.f, ss = 0.f;
#pragma unroll
    for (int i = 0; i < 3; i++) {
        int j = tid + i * 256;
        v[i] = pr[j];
        s += v[i]; ss += v[i] * v[i];
    }
    __shared__ float sh[256], sh2[256];
    sh[tid] = s; sh2[tid] = ss;
    __syncthreads();
    for (int o = 128; o > 0; o >>= 1) {
        if (tid < o) { sh[tid] += sh[tid + o]; sh2[tid] += sh2[tid + o]; }
        __syncthreads();
    }
    __shared__ float smean, srstd;
    if (tid == 0) {
        float m = sh[0] / (float)OUTD;
        float var = sh2[0] / (float)OUTD - m * m;
        smean = m; srstd = rsqrtf(var + LN_EPS);
    }
    __syncthreads();
    float t[3];
    float tss = 0.f;
#pragma unroll
    for (int i = 0; i < 3; i++) {
        int j = tid + i * 256;
        t[i] = (v[i] - smean) * srstd * g[j] + b[j];
        tss += t[i] * t[i];
    }
    __syncthreads();
    sh[tid] = tss;
    __syncthreads();
    for (int o = 128; o > 0; o >>= 1) {
        if (tid < o) sh[tid] += sh[tid + o];
        __syncthreads();
    }
    __shared__ float sinv;
    if (tid == 0) sinv = 1.f / sqrtf(sh[0]);
    __syncthreads();
    float* pw = pred + (size_t)row * OUTD;
#pragma unroll
    for (int i = 0; i < 3; i++) {
        int j = tid + i * 256;
        pw[j] = t[i];
        float pn = t[i] * sinv;
        __nv_bfloat16 h, l;
        split_bf16(pn, h, l);
        size_t o = (size_t)row * OUTD + j;
        g_PNh[o] = h; g_PNl[o] = l;
    }
}

__global__ void ynorm_kernel(const float* __restrict__ y)
{
    int row = blockIdx.x, tid = threadIdx.x;
    const float* yr = y + (size_t)row * OUTD;
    float v[3];
    float ss = 0.f;
#pragma unroll
    for (int i = 0; i < 3; i++) {
        int j = tid + i * 256;
        v[i] = yr[j];
        ss += v[i] * v[i];
    }
    __shared__ float sh[256];
    sh[tid] = ss;
    __syncthreads();
    for (int o = 128; o > 0; o >>= 1) {
        if (tid < o) sh[tid] += sh[tid + o];
        __syncthreads();
    }
    __shared__ float sinv;
    if (tid == 0) sinv = 1.f / sqrtf(sh[0]);
    __syncthreads();
#pragma unroll
    for (int i = 0; i < 3; i++) {
        int j = tid + i * 256;
        float yn = v[i] * sinv;
        __nv_bfloat16 h, l;
        split_bf16(yn, h, l);
        size_t o = (size_t)row * OUTD + j;
        g_YNh[o] = h; g_YNl[o] = l;
    }
}

// ===========================================================================
// Reduce S: per-row argmax (first occurrence) + logsumexp.
// ===========================================================================
__global__ void reduce_S_kernel()
{
    int row = blockIdx.x, tid = threadIdx.x;
    const float* sr = g_S + (size_t)row * BSZ;

    float best = -3.4e38f;
    int bidx = 0x7fffffff;
    for (int j = tid; j < BSZ; j += 256) {
        float v = sr[j];
        if (v > best || (v == best && j < bidx)) { best = v; bidx = j; }
    }
    __shared__ float shv[256];
    __shared__ int   shi[256];
    shv[tid] = best; shi[tid] = bidx;
    __syncthreads();
    for (int o = 128; o > 0; o >>= 1) {
        if (tid < o) {
            float vo = shv[tid + o]; int io = shi[tid + o];
            if (vo > shv[tid] || (vo == shv[tid] && io < shi[tid])) {
                shv[tid] = vo; shi[tid] = io;
            }
        }
        __syncthreads();
    }
    __shared__ float smax;
    __shared__ int   samax;
    if (tid == 0) { smax = shv[0]; samax = shi[0]; }
    __syncthreads();

    float se = 0.f;
    for (int j = tid; j < BSZ; j += 256) se += __expf(sr[j] - smax);
    shv[tid] = se;
    __syncthreads();
    for (int o = 128; o > 0; o >>= 1) {
        if (tid < o) shv[tid] += shv[tid + o];
        __syncthreads();
    }
    if (tid == 0) {
        float lse = smax + __logf(shv[0]);
        double contrib = (double)lse - (double)sr[row];
        atomicAdd(&g_loss, contrib);
        if (samax == row) atomicAdd(&g_correct, 1);
    }
}

__global__ void finalize_kernel(float* __restrict__ out, int out_size)
{
    const int NP = BSZ * OUTD;
    if (out_size >= NP + 2) {
        out[NP]     = (float)g_loss;
        out[NP + 1] = (float)g_correct / (float)BSZ;
    }
}

// ===========================================================================
extern "C" void kernel_launch(void* const* d_in, const int* in_sizes, int n_in,
                              void* d_out, int out_size)
{
    const float* inp  = (const float*)d_in[0];
    const float* y    = (const float*)d_in[1];
    const float* ln1g = (const float*)d_in[2];
    const float* ln1b = (const float*)d_in[3];
    const float* W1   = (const float*)d_in[4];
    const float* b1   = (const float*)d_in[5];
    const float* Wa   = (const float*)d_in[6];
    const float* ba   = (const float*)d_in[7];
    const float* Wb   = (const float*)d_in[8];
    const float* bb   = (const float*)d_in[9];
    const float* W2   = (const float*)d_in[10];
    const float* b2   = (const float*)d_in[11];
    const float* ln2g = (const float*)d_in[12];
    const float* ln2b = (const float*)d_in[13];
    float* out = (float*)d_out;

    static int smem_cfg_done = 0;
    if (!smem_cfg_done) {
        cudaFuncSetAttribute(tc_gemm, cudaFuncAttributeMaxDynamicSharedMemorySize,
                             GEMM_SMEM_BYTES);
        smem_cfg_done = 1;
    }

    float *H, *P, *S;
    cudaGetSymbolAddress((void**)&H, g_H);
    cudaGetSymbolAddress((void**)&P, g_P);
    cudaGetSymbolAddress((void**)&S, g_S);
    __nv_bfloat16 *A1h, *A1l, *Hh, *Hl, *Th, *Tl, *PNh, *PNl, *YNh, *YNl;
    __nv_bfloat16 *W1h, *W1l, *Wah, *Wal, *Wbh, *Wbl, *W2h, *W2l;
    cudaGetSymbolAddress((void**)&A1h, g_A1h);
    cudaGetSymbolAddress((void**)&A1l, g_A1l);
    cudaGetSymbolAddress((void**)&Hh,  g_Hh);
    cudaGetSymbolAddress((void**)&Hl,  g_Hl);
    cudaGetSymbolAddress((void**)&Th,  g_Th);
    cudaGetSymbolAddress((void**)&Tl,  g_Tl);
    cudaGetSymbolAddress((void**)&PNh, g_PNh);
    cudaGetSymbolAddress((void**)&PNl, g_PNl);
    cudaGetSymbolAddress((void**)&YNh, g_YNh);
    cudaGetSymbolAddress((void**)&YNl, g_YNl);
    cudaGetSymbolAddress((void**)&W1h, g_W1h);
    cudaGetSymbolAddress((void**)&W1l, g_W1l);
    cudaGetSymbolAddress((void**)&Wah, g_Wah);
    cudaGetSymbolAddress((void**)&Wal, g_Wal);
    cudaGetSymbolAddress((void**)&Wbh, g_Wbh);
    cudaGetSymbolAddress((void**)&Wbl, g_Wbl);
    cudaGetSymbolAddress((void**)&W2h, g_W2h);
    cudaGetSymbolAddress((void**)&W2l, g_W2l);

    const int NSM = 152;
    auto grid_for = [&](int M, int N) {
        int nt = (M >> 8) * (N >> 7);
        return nt < NSM ? nt : NSM;
    };

    // 0: all weight transposes+splits in one launch
    tsplit_all_kernel<<<dim3(INPD / 32, HIDD / 32, 4), dim3(32, 8)>>>(W1, Wa, Wb, W2);

    // 1: LN1 + split input (+ zero accumulators)
    ln1_split_kernel<<<BSZ, 256>>>(inp, ln1g, ln1b);

    // 2: H = LN1(inp) @ W1 + b1   [8192,1024] K=3072 -> f32 H + pair
    tc_gemm<<<grid_for(BSZ, HIDD), 256, GEMM_SMEM_BYTES>>>(
        A1h, A1l, W1h, W1l, b1, nullptr, H, Hh, Hl, BSZ, HIDD, INPD, 0);

    // 3-6: residual blocks (shared weights), x2
    for (int r = 0; r < 2; r++) {
        tc_gemm<<<grid_for(BSZ, HIDD), 256, GEMM_SMEM_BYTES>>>(
            Hh, Hl, Wah, Wal, ba, nullptr, nullptr, Th, Tl, BSZ, HIDD, HIDD, 1);
        tc_gemm<<<grid_for(BSZ, HIDD), 256, GEMM_SMEM_BYTES>>>(
            Th, Tl, Wbh, Wbl, bb, H, H, Hh, Hl, BSZ, HIDD, HIDD, 1);
    }

    // 7: P = H @ W2 + b2   [8192,768] K=1024 -> f32 only
    tc_gemm<<<grid_for(BSZ, OUTD), 256, GEMM_SMEM_BYTES>>>(
        Hh, Hl, W2h, W2l, b2, nullptr, P, nullptr, nullptr, BSZ, OUTD, HIDD, 0);

    // 8-9: pred = LN2(P); PN pair; YN pair
    ln2_norm_kernel<<<BSZ, 256>>>(P, ln2g, ln2b, out);
    ynorm_kernel<<<BSZ, 256>>>(y);

    // 10: S = PN @ YN^T   [8192,8192] K=768 -> f32
    tc_gemm<<<grid_for(BSZ, BSZ), 256, GEMM_SMEM_BYTES>>>(
        PNh, PNl, YNh, YNl, nullptr, nullptr, S, nullptr, nullptr, BSZ, BSZ, OUTD, 0);

    // 11-12: reduce + finalize
    reduce_S_kernel<<<BSZ, 256>>>();
    finalize_kernel<<<1, 1>>>(out, out_size);
}